// round 1
// baseline (speedup 1.0000x reference)
#include <cuda_runtime.h>
#include <cuda_bf16.h>

// ---------------------------------------------------------------------------
// Problem constants
// ---------------------------------------------------------------------------
#define B_ 2
#define S_ 2048
#define H_ 16
#define D_ 128
#define HID_ 2048
#define M_ (B_ * S_)   // 4096

// Scratch (device globals — allocation-free per harness rules)
__device__ float g_q[(size_t)B_ * H_ * S_ * D_];   // [b,h,s,d]
__device__ float g_k[(size_t)B_ * H_ * S_ * D_];
__device__ float g_v[(size_t)B_ * H_ * S_ * D_];
__device__ float g_ao[(size_t)M_ * HID_];          // [b,s,h*D+d]

// ---------------------------------------------------------------------------
// Packed f32x2 helpers (sm_103a: 3-reg FFMA is half-rate; f32x2 restores peak)
// ---------------------------------------------------------------------------
__device__ __forceinline__ void ffma2(unsigned long long& acc,
                                      unsigned long long a,
                                      unsigned long long b) {
    asm("fma.rn.f32x2 %0, %1, %2, %0;" : "+l"(acc) : "l"(a), "l"(b));
}
__device__ __forceinline__ unsigned long long pack2(float x, float y) {
    unsigned long long r;
    asm("mov.b64 %0, {%1, %2};" : "=l"(r) : "f"(x), "f"(y));
    return r;
}
__device__ __forceinline__ float2 unpack2(unsigned long long v) {
    float lo, hi;
    asm("mov.b64 {%0, %1}, %2;" : "=f"(lo), "=f"(hi) : "l"(v));
    return make_float2(lo, hi);
}
__device__ __forceinline__ unsigned long long mul2(unsigned long long a,
                                                   unsigned long long b) {
    unsigned long long r;
    asm("mul.rn.f32x2 %0, %1, %2;" : "=l"(r) : "l"(a), "l"(b));
    return r;
}

// ---------------------------------------------------------------------------
// GEMM: C[M,N] = A[M,K] * W[K,N], M=4096, N=K=2048.
// 128x128 block, BK=16, 256 threads, 8x8 frag per thread, f32x2 accumulators.
// OUT==0: A = g_ao, write row-major to Cout (final O projection)
// OUT==1/2/3: A = Ain (hidden_states), write to g_q/g_k/g_v in [b,h,s,d]
// ---------------------------------------------------------------------------
template <int OUT>
__global__ __launch_bounds__(256, 2) void gemm128(const float* __restrict__ Ain,
                                                  const float* __restrict__ W,
                                                  float* __restrict__ Cout) {
    __shared__ float As[16][132];   // A^T tile: As[k][m], padded
    __shared__ float Bs[16][128];   // B tile:  Bs[k][n]

    const float* A = (OUT == 0) ? (const float*)g_ao : Ain;

    const int t = threadIdx.x;
    const int tx = t & 15;
    const int ty = t >> 4;
    const int m0 = blockIdx.y * 128;
    const int n0 = blockIdx.x * 128;

    unsigned long long acc[8][4];
#pragma unroll
    for (int i = 0; i < 8; i++)
#pragma unroll
        for (int j = 0; j < 4; j++) acc[i][j] = 0ULL;   // (0.f, 0.f)

    for (int k0 = 0; k0 < HID_; k0 += 16) {
        // Load A tile 128x16, store transposed
#pragma unroll
        for (int i = 0; i < 2; i++) {
            int x = t + i * 256;            // 0..511 (128 rows x 4 float4)
            int row = x >> 2;
            int k4 = (x & 3) * 4;
            float4 v = *(const float4*)(A + (size_t)(m0 + row) * HID_ + k0 + k4);
            As[k4 + 0][row] = v.x;
            As[k4 + 1][row] = v.y;
            As[k4 + 2][row] = v.z;
            As[k4 + 3][row] = v.w;
        }
        // Load B tile 16x128 natural
#pragma unroll
        for (int i = 0; i < 2; i++) {
            int x = t + i * 256;            // 0..511 (16 rows x 32 float4)
            int row = x >> 5;
            int c4 = (x & 31) * 4;
            *(float4*)(&Bs[row][c4]) =
                *(const float4*)(W + (size_t)(k0 + row) * HID_ + n0 + c4);
        }
        __syncthreads();

#pragma unroll
        for (int kk = 0; kk < 16; kk++) {
            float4 a0 = *(const float4*)(&As[kk][ty * 4]);
            float4 a1 = *(const float4*)(&As[kk][ty * 4 + 64]);
            ulonglong2 b0 = *(const ulonglong2*)(&Bs[kk][tx * 4]);
            ulonglong2 b1 = *(const ulonglong2*)(&Bs[kk][tx * 4 + 64]);
            unsigned long long bb[4] = {b0.x, b0.y, b1.x, b1.y};
            float av[8] = {a0.x, a0.y, a0.z, a0.w, a1.x, a1.y, a1.z, a1.w};
#pragma unroll
            for (int i = 0; i < 8; i++) {
                unsigned long long aa = pack2(av[i], av[i]);
#pragma unroll
                for (int j = 0; j < 4; j++) ffma2(acc[i][j], aa, bb[j]);
            }
        }
        __syncthreads();
    }

    // Epilogue
#pragma unroll
    for (int i = 0; i < 8; i++) {
        int lm = (i < 4) ? (ty * 4 + i) : (64 + ty * 4 + (i - 4));
        int gm = m0 + lm;
        float c[8];
#pragma unroll
        for (int j = 0; j < 4; j++) {
            float2 f = unpack2(acc[i][j]);
            c[2 * j] = f.x;
            c[2 * j + 1] = f.y;
        }
        if (OUT == 0) {
            size_t base = (size_t)gm * HID_ + n0;
            *(float4*)(Cout + base + tx * 4) = make_float4(c[0], c[1], c[2], c[3]);
            *(float4*)(Cout + base + tx * 4 + 64) = make_float4(c[4], c[5], c[6], c[7]);
        } else {
            float* dst = (OUT == 1) ? g_q : (OUT == 2) ? g_k : g_v;
            int bb_ = gm >> 11;          // / 2048
            int ss = gm & (S_ - 1);
            int h = blockIdx.x;          // BN == D, one head per n-block
            size_t base = (((size_t)bb_ * H_ + h) * S_ + ss) * D_;
            *(float4*)(dst + base + tx * 4) = make_float4(c[0], c[1], c[2], c[3]);
            *(float4*)(dst + base + tx * 4 + 64) = make_float4(c[4], c[5], c[6], c[7]);
        }
    }
}

// ---------------------------------------------------------------------------
// RoPE over Q and K in-place. One thread handles the (d, d+64) pair for both.
// ---------------------------------------------------------------------------
__global__ void rope_kernel(const float* __restrict__ cosb,
                            const float* __restrict__ sinb) {
    int tid = blockIdx.x * 256 + threadIdx.x;   // B*H*S*64 threads
    int d = tid & 63;
    int s = (tid >> 6) & (S_ - 1);
    int bh = tid >> 17;                          // / (2048*64)
    size_t base = ((size_t)bh * S_ + s) * D_;
    float c0 = cosb[s * D_ + d], c1 = cosb[s * D_ + d + 64];
    float s0 = sinb[s * D_ + d], s1 = sinb[s * D_ + d + 64];

    float q0 = g_q[base + d], q1 = g_q[base + d + 64];
    g_q[base + d] = q0 * c0 - q1 * s0;          // x1*cos + (-x2)*sin
    g_q[base + d + 64] = q1 * c1 + q0 * s1;     // x2*cos + ( x1)*sin

    float k0 = g_k[base + d], k1 = g_k[base + d + 64];
    g_k[base + d] = k0 * c0 - k1 * s0;
    g_k[base + d + 64] = k1 * c1 + k0 * s1;
}

// ---------------------------------------------------------------------------
// Flash attention, fp32. Per block: 128 queries of one (b,h); loop over 2048
// keys in tiles of 128. 256 threads, 8x8 frags, f32x2 FMA throughout.
// SMEM: Qs = Q^T [d][m] (pitch 132), Ks = K^T [d][n] (reused as P^T [c][m]),
//       Vs = V [c][d] (pitch 132). 198 KB dynamic.
// ---------------------------------------------------------------------------
__global__ __launch_bounds__(256, 1) void attn_kernel() {
    extern __shared__ float sm_[];
    float* Qs = sm_;                  // 128*132
    float* Ks = sm_ + 128 * 132;      // K^T, then P^T
    float* Vs = sm_ + 2 * 128 * 132;  // V natural

    const int t = threadIdx.x, tx = t & 15, ty = t >> 4;
    const int bh = blockIdx.y;
    const int q0 = blockIdx.x * 128;
    const float* Qg = g_q + ((size_t)bh * S_ + q0) * D_;
    const float* Kg = g_k + (size_t)bh * S_ * D_;
    const float* Vg = g_v + (size_t)bh * S_ * D_;

    // Load Q tile transposed: Qs[d][m]
#pragma unroll
    for (int i = 0; i < 16; i++) {
        int x = t + i * 256;           // 0..4095 (128 rows x 32 float4)
        int row = x >> 5;
        int d4 = (x & 31) * 4;
        float4 v = *(const float4*)(Qg + (size_t)row * D_ + d4);
        Qs[(d4 + 0) * 132 + row] = v.x;
        Qs[(d4 + 1) * 132 + row] = v.y;
        Qs[(d4 + 2) * 132 + row] = v.z;
        Qs[(d4 + 3) * 132 + row] = v.w;
    }

    float mI[8], lI[8];
    unsigned long long O2[8][4];
#pragma unroll
    for (int i = 0; i < 8; i++) {
        mI[i] = -1e30f;
        lI[i] = 0.f;
#pragma unroll
        for (int j = 0; j < 4; j++) O2[i][j] = 0ULL;
    }

    const float scale = 0.088388347648318447f;   // 1/sqrt(128)

    for (int kt = 0; kt < S_ / 128; kt++) {
        const float* Kt = Kg + (size_t)kt * 128 * D_;
        const float* Vt = Vg + (size_t)kt * 128 * D_;
        __syncthreads();   // prior PV finished with Ks/Vs (covers Qs on kt==0)
#pragma unroll
        for (int i = 0; i < 16; i++) {
            int x = t + i * 256;
            int row = x >> 5;
            int d4 = (x & 31) * 4;
            float4 v = *(const float4*)(Kt + (size_t)row * D_ + d4);
            Ks[(d4 + 0) * 132 + row] = v.x;
            Ks[(d4 + 1) * 132 + row] = v.y;
            Ks[(d4 + 2) * 132 + row] = v.z;
            Ks[(d4 + 3) * 132 + row] = v.w;
            float4 w = *(const float4*)(Vt + (size_t)row * D_ + d4);
            *(float4*)(Vs + (size_t)row * 132 + d4) = w;
        }
        __syncthreads();

        // ---- S = Q K^T (128x128), frag 8x8 per thread ----
        unsigned long long Sa[8][4];
#pragma unroll
        for (int i = 0; i < 8; i++)
#pragma unroll
            for (int j = 0; j < 4; j++) Sa[i][j] = 0ULL;

#pragma unroll 4
        for (int d = 0; d < 128; d++) {
            float4 a0 = *(const float4*)(Qs + d * 132 + ty * 4);
            float4 a1 = *(const float4*)(Qs + d * 132 + ty * 4 + 64);
            ulonglong2 b0 = *(const ulonglong2*)(Ks + d * 132 + tx * 4);
            ulonglong2 b1 = *(const ulonglong2*)(Ks + d * 132 + tx * 4 + 64);
            unsigned long long bb[4] = {b0.x, b0.y, b1.x, b1.y};
            float av[8] = {a0.x, a0.y, a0.z, a0.w, a1.x, a1.y, a1.z, a1.w};
#pragma unroll
            for (int i = 0; i < 8; i++) {
                unsigned long long aa = pack2(av[i], av[i]);
#pragma unroll
                for (int j = 0; j < 4; j++) ffma2(Sa[i][j], aa, bb[j]);
            }
        }

        // Unpack S
        float P[8][8];
#pragma unroll
        for (int i = 0; i < 8; i++)
#pragma unroll
            for (int j = 0; j < 4; j++) {
                float2 f = unpack2(Sa[i][j]);
                P[i][2 * j] = f.x;
                P[i][2 * j + 1] = f.y;
            }

        __syncthreads();   // everyone done reading Ks before it becomes P^T

        // ---- online softmax (row groups share ty: lanes tx 0..15, shfl) ----
#pragma unroll
        for (int i = 0; i < 8; i++) {
            float rm = P[i][0];
#pragma unroll
            for (int j = 1; j < 8; j++) rm = fmaxf(rm, P[i][j]);
#pragma unroll
            for (int off = 8; off > 0; off >>= 1)
                rm = fmaxf(rm, __shfl_xor_sync(0xffffffffu, rm, off));
            rm *= scale;
            float mnew = fmaxf(mI[i], rm);
            float alpha = __expf(mI[i] - mnew);
            float rs = 0.f;
#pragma unroll
            for (int j = 0; j < 8; j++) {
                float p = __expf(P[i][j] * scale - mnew);
                P[i][j] = p;
                rs += p;
            }
#pragma unroll
            for (int off = 8; off > 0; off >>= 1)
                rs += __shfl_xor_sync(0xffffffffu, rs, off);
            lI[i] = lI[i] * alpha + rs;
            mI[i] = mnew;
            unsigned long long al2 = pack2(alpha, alpha);
#pragma unroll
            for (int j = 0; j < 4; j++) O2[i][j] = mul2(O2[i][j], al2);
        }

        // ---- store P^T into Ks buffer: Ps[c][m] ----
#pragma unroll
        for (int g = 0; g < 2; g++) {
            int mrow = ty * 4 + g * 64;
#pragma unroll
            for (int j = 0; j < 8; j++) {
                int c = (j < 4) ? (tx * 4 + j) : (64 + tx * 4 + (j - 4));
                *(float4*)(Ks + (size_t)c * 132 + mrow) =
                    make_float4(P[g * 4 + 0][j], P[g * 4 + 1][j],
                                P[g * 4 + 2][j], P[g * 4 + 3][j]);
            }
        }
        __syncthreads();

        // ---- O += P V ----
#pragma unroll 4
        for (int c = 0; c < 128; c++) {
            float4 a0 = *(const float4*)(Ks + c * 132 + ty * 4);
            float4 a1 = *(const float4*)(Ks + c * 132 + ty * 4 + 64);
            ulonglong2 b0 = *(const ulonglong2*)(Vs + c * 132 + tx * 4);
            ulonglong2 b1 = *(const ulonglong2*)(Vs + c * 132 + tx * 4 + 64);
            unsigned long long bb[4] = {b0.x, b0.y, b1.x, b1.y};
            float av[8] = {a0.x, a0.y, a0.z, a0.w, a1.x, a1.y, a1.z, a1.w};
#pragma unroll
            for (int i = 0; i < 8; i++) {
                unsigned long long aa = pack2(av[i], av[i]);
#pragma unroll
                for (int j = 0; j < 4; j++) ffma2(O2[i][j], aa, bb[j]);
            }
        }
    }

    // ---- finalize: O / l, write to g_ao [b,s,h*D+d] ----
    const int b_ = bh >> 4, h = bh & 15;
#pragma unroll
    for (int i = 0; i < 8; i++) {
        int lm = (i < 4) ? (ty * 4 + i) : (64 + ty * 4 + (i - 4));
        int srow = q0 + lm;
        float inv = 1.0f / lI[i];
        float c[8];
#pragma unroll
        for (int j = 0; j < 4; j++) {
            float2 f = unpack2(O2[i][j]);
            c[2 * j] = f.x * inv;
            c[2 * j + 1] = f.y * inv;
        }
        size_t base = ((size_t)b_ * S_ + srow) * HID_ + h * D_;
        *(float4*)(g_ao + base + tx * 4) = make_float4(c[0], c[1], c[2], c[3]);
        *(float4*)(g_ao + base + tx * 4 + 64) = make_float4(c[4], c[5], c[6], c[7]);
    }
}

// ---------------------------------------------------------------------------
// Launch
// ---------------------------------------------------------------------------
extern "C" void kernel_launch(void* const* d_in, const int* in_sizes, int n_in,
                              void* d_out, int out_size) {
    const float* X = (const float*)d_in[0];     // hidden_states [b,s,HID]
    const float* cosb = (const float*)d_in[1];  // [1,1,s,D]
    const float* sinb = (const float*)d_in[2];
    const float* Wq = (const float*)d_in[3];
    const float* Wk = (const float*)d_in[4];
    const float* Wv = (const float*)d_in[5];
    const float* Wo = (const float*)d_in[6];
    float* out = (float*)d_out;

    dim3 ggrid(HID_ / 128, M_ / 128);   // (16, 32)

    gemm128<1><<<ggrid, 256>>>(X, Wq, nullptr);
    gemm128<2><<<ggrid, 256>>>(X, Wk, nullptr);
    gemm128<3><<<ggrid, 256>>>(X, Wv, nullptr);

    rope_kernel<<<(B_ * H_ * S_ * 64) / 256, 256>>>(cosb, sinb);

    const int smem_bytes = 3 * 128 * 132 * (int)sizeof(float);   // 202752
    cudaFuncSetAttribute(attn_kernel,
                         cudaFuncAttributeMaxDynamicSharedMemorySize, smem_bytes);
    attn_kernel<<<dim3(S_ / 128, B_ * H_), 256, smem_bytes>>>();

    gemm128<0><<<ggrid, 256>>>(nullptr, Wo, out);
}

// round 3
// speedup vs baseline: 1.4114x; 1.4114x over previous
#include <cuda_runtime.h>
#include <cuda_bf16.h>
#include <cstdint>

// ---------------------------------------------------------------------------
// Problem constants
// ---------------------------------------------------------------------------
#define B_ 2
#define S_ 2048
#define H_ 16
#define D_ 128
#define HID_ 2048
#define M_ (B_ * S_)   // 4096

// Scratch (device globals — allocation-free per harness rules)
__device__ float g_q[(size_t)B_ * H_ * S_ * D_];   // [b,h,s,d]
__device__ float g_k[(size_t)B_ * H_ * S_ * D_];
__device__ float g_v[(size_t)B_ * H_ * S_ * D_];
__device__ float g_ao[(size_t)M_ * HID_];          // [b,s,h*D+d]

// bf16 split buffers: activations (A) and one weight (B, transposed to [N][K])
__device__ __nv_bfloat16 g_xhi[(size_t)M_ * HID_];
__device__ __nv_bfloat16 g_xlo[(size_t)M_ * HID_];
__device__ __nv_bfloat16 g_bhi[(size_t)HID_ * HID_];
__device__ __nv_bfloat16 g_blo[(size_t)HID_ * HID_];

// ---------------------------------------------------------------------------
// PTX helpers (all non-'a' features: ldmatrix sm_75, mma bf16 sm_80, cp.async)
// ---------------------------------------------------------------------------
__device__ __forceinline__ uint32_t smem_u32(const void* p) {
    uint32_t a;
    asm("{ .reg .u64 t; cvta.to.shared.u64 t, %1; cvt.u32.u64 %0, t; }"
        : "=r"(a) : "l"(p));
    return a;
}
__device__ __forceinline__ void cpa16(uint32_t s, const void* g) {
    asm volatile("cp.async.cg.shared.global [%0], [%1], 16;" :: "r"(s), "l"(g));
}
#define CP_COMMIT() asm volatile("cp.async.commit_group;" ::: "memory")
#define CP_WAIT0()  asm volatile("cp.async.wait_group 0;" ::: "memory")

#define LDSM4(r, addr)                                                        \
    asm volatile("ldmatrix.sync.aligned.m8n8.x4.shared.b16 {%0,%1,%2,%3}, [%4];" \
                 : "=r"((r)[0]), "=r"((r)[1]), "=r"((r)[2]), "=r"((r)[3])     \
                 : "r"(addr))

#define MMA16816(d, a, b)                                                     \
    asm volatile(                                                             \
        "mma.sync.aligned.m16n8k16.row.col.f32.bf16.bf16.f32 "                \
        "{%0,%1,%2,%3}, {%4,%5,%6,%7}, {%8,%9}, {%0,%1,%2,%3};"               \
        : "+f"((d)[0]), "+f"((d)[1]), "+f"((d)[2]), "+f"((d)[3])              \
        : "r"((a)[0]), "r"((a)[1]), "r"((a)[2]), "r"((a)[3]),                 \
          "r"((b)[0]), "r"((b)[1]))

// ---------------------------------------------------------------------------
// Packed f32x2 helpers (attention kernel)
// ---------------------------------------------------------------------------
__device__ __forceinline__ void ffma2(unsigned long long& acc,
                                      unsigned long long a,
                                      unsigned long long b) {
    asm("fma.rn.f32x2 %0, %1, %2, %0;" : "+l"(acc) : "l"(a), "l"(b));
}
__device__ __forceinline__ unsigned long long pack2(float x, float y) {
    unsigned long long r;
    asm("mov.b64 %0, {%1, %2};" : "=l"(r) : "f"(x), "f"(y));
    return r;
}
__device__ __forceinline__ float2 unpack2(unsigned long long v) {
    float lo, hi;
    asm("mov.b64 {%0, %1}, %2;" : "=f"(lo), "=f"(hi) : "l"(v));
    return make_float2(lo, hi);
}
__device__ __forceinline__ unsigned long long mul2(unsigned long long a,
                                                   unsigned long long b) {
    unsigned long long r;
    asm("mul.rn.f32x2 %0, %1, %2;" : "=l"(r) : "l"(a), "l"(b));
    return r;
}

// ---------------------------------------------------------------------------
// Conversion kernels: fp32 -> bf16 hi/lo split
// ---------------------------------------------------------------------------
__device__ __forceinline__ void split1(float x, unsigned short& h, unsigned short& l) {
    __nv_bfloat16 hb = __float2bfloat16(x);
    __nv_bfloat16 lb = __float2bfloat16(x - __bfloat162float(hb));
    h = __bfloat16_as_ushort(hb);
    l = __bfloat16_as_ushort(lb);
}

// Activations: src [M,K] fp32 -> g_xhi/g_xlo [M,K] bf16. src==nullptr -> g_ao.
__global__ void asplit_kernel(const float* __restrict__ src) {
    const float* s = src ? src : (const float*)g_ao;
    size_t i = (size_t)blockIdx.x * 256 + threadIdx.x;   // over elems/4
    float4 v = ((const float4*)s)[i];
    ushort4 h, l;
    split1(v.x, h.x, l.x);
    split1(v.y, h.y, l.y);
    split1(v.z, h.z, l.z);
    split1(v.w, h.w, l.w);
    ((ushort4*)g_xhi)[i] = h;
    ((ushort4*)g_xlo)[i] = l;
}

// Weights: W [K,N] fp32 -> g_bhi/g_blo [N,K] bf16 (transposed)
__global__ void wsplit_kernel(const float* __restrict__ W) {
    __shared__ float ts[32][33];
    const int tx = threadIdx.x, ty = threadIdx.y;       // 32 x 8
    const int n0 = blockIdx.x * 32, k0 = blockIdx.y * 32;
#pragma unroll
    for (int i = 0; i < 4; i++)
        ts[ty + 8 * i][tx] = W[(size_t)(k0 + ty + 8 * i) * HID_ + n0 + tx];
    __syncthreads();
#pragma unroll
    for (int i = 0; i < 4; i++) {
        int n = n0 + ty + 8 * i;
        int k = k0 + tx;
        float v = ts[tx][ty + 8 * i];
        unsigned short h, l;
        split1(v, h, l);
        g_bhi[(size_t)n * HID_ + k] = __ushort_as_bfloat16(h);
        g_blo[(size_t)n * HID_ + k] = __ushort_as_bfloat16(l);
    }
}

// ---------------------------------------------------------------------------
// mma.sync bf16x3 GEMM: C[M,N] = A[M,K] * B^T[N,K], fp32-accurate (~2^-16).
// CTA tile 128x128, BK=64, 256 threads (warp grid 4m x 2n, warp tile 32x64).
// SMEM per buffer: Ah,Al,Bh,Bl each 128 rows x 144B pitch (128B data) = 18KB.
// Double-buffered via cp.async. Frags via ldmatrix.x4 (conflict-free: pitch
// 144B = 9 chunks mod 32).
// OUT==0: write row-major to Cout. OUT==1/2/3: write g_q/g_k/g_v [b,h,s,d].
// ---------------------------------------------------------------------------
#define PITCH 144
#define MATB  (128 * PITCH)          // 18432 bytes per matrix
#define BUFB  (4 * MATB)             // 73728 bytes per buffer
#define GEMM_SMEM (2 * BUFB)         // 147456

template <int OUT>
__global__ __launch_bounds__(256, 1) void mma_gemm(float* __restrict__ Cout) {
    extern __shared__ char dsm[];
    const uint32_t sb = smem_u32(dsm);
    const int t = threadIdx.x;
    const int lane = t & 31, wid = t >> 5;
    const int wm = wid & 3, wn = wid >> 2;
    const int m0 = blockIdx.y * 128, n0 = blockIdx.x * 128;

    const __nv_bfloat16* __restrict__ AH = g_xhi;
    const __nv_bfloat16* __restrict__ AL = g_xlo;
    const __nv_bfloat16* __restrict__ BH = g_bhi;
    const __nv_bfloat16* __restrict__ BL = g_blo;

    float acc[2][8][4];
#pragma unroll
    for (int i = 0; i < 2; i++)
#pragma unroll
        for (int j = 0; j < 8; j++)
#pragma unroll
            for (int k = 0; k < 4; k++) acc[i][j][k] = 0.f;

    // per-thread load slots: idx = t + j*256 -> row = idx>>3, chunk = idx&7
    const int lrow = t >> 3;
    const int lch = t & 7;

    // prologue: load buffer 0 (k0 = 0)
    {
        const uint32_t base = sb;
#pragma unroll
        for (int j = 0; j < 4; j++) {
            int row = lrow + j * 32;
            uint32_t sa = base + row * PITCH + lch * 16;
            size_t ga = (size_t)(m0 + row) * HID_ + lch * 8;
            size_t gb = (size_t)(n0 + row) * HID_ + lch * 8;
            cpa16(sa, AH + ga);
            cpa16(sa + MATB, AL + ga);
            cpa16(sa + 2 * MATB, BH + gb);
            cpa16(sa + 3 * MATB, BL + gb);
        }
        CP_COMMIT();
    }

    const uint32_t lm_a_off =
        (uint32_t)((wm * 32 + (lane & 15)) * PITCH + (lane >> 4) * 16);
    const uint32_t lm_b_off =
        (uint32_t)((wn * 64 + (lane & 15)) * PITCH + (lane >> 4) * 16);

    for (int c = 0; c < HID_ / 64; c++) {
        CP_WAIT0();
        __syncthreads();

        if (c + 1 < HID_ / 64) {
            const uint32_t base = sb + ((c + 1) & 1) * BUFB;
            const int k0 = (c + 1) * 64;
#pragma unroll
            for (int j = 0; j < 4; j++) {
                int row = lrow + j * 32;
                uint32_t sa = base + row * PITCH + lch * 16;
                size_t ga = (size_t)(m0 + row) * HID_ + k0 + lch * 8;
                size_t gb = (size_t)(n0 + row) * HID_ + k0 + lch * 8;
                cpa16(sa, AH + ga);
                cpa16(sa + MATB, AL + ga);
                cpa16(sa + 2 * MATB, BH + gb);
                cpa16(sa + 3 * MATB, BL + gb);
            }
            CP_COMMIT();
        }

        const uint32_t cb = sb + (c & 1) * BUFB;
#pragma unroll
        for (int ks = 0; ks < 4; ks++) {
            uint32_t ah[2][4], al[2][4];
#pragma unroll
            for (int mt = 0; mt < 2; mt++) {
                uint32_t addr = cb + lm_a_off + mt * (16 * PITCH) + ks * 32;
                LDSM4(ah[mt], addr);
                LDSM4(al[mt], addr + MATB);
            }
            uint32_t bh[8][2], bl[8][2];
#pragma unroll
            for (int np = 0; np < 4; np++) {
                uint32_t addr = cb + 2 * MATB + lm_b_off + np * (16 * PITCH) + ks * 32;
                uint32_t r[4];
                LDSM4(r, addr);
                bh[2 * np][0] = r[0]; bh[2 * np + 1][0] = r[1];
                bh[2 * np][1] = r[2]; bh[2 * np + 1][1] = r[3];
                LDSM4(r, addr + MATB);
                bl[2 * np][0] = r[0]; bl[2 * np + 1][0] = r[1];
                bl[2 * np][1] = r[2]; bl[2 * np + 1][1] = r[3];
            }
#pragma unroll
            for (int mt = 0; mt < 2; mt++)
#pragma unroll
                for (int nt = 0; nt < 8; nt++) {
                    MMA16816(acc[mt][nt], ah[mt], bh[nt]);
                    MMA16816(acc[mt][nt], al[mt], bh[nt]);
                    MMA16816(acc[mt][nt], ah[mt], bl[nt]);
                }
        }
        __syncthreads();
    }

    // Epilogue: thread (lane) holds rows qrow,qrow+8; cols qcol,qcol+1 per tile
    const int qrow = lane >> 2;
    const int qcol = (lane & 3) * 2;
#pragma unroll
    for (int mt = 0; mt < 2; mt++) {
#pragma unroll
        for (int half = 0; half < 2; half++) {
            const int m = m0 + wm * 32 + mt * 16 + qrow + half * 8;
            float* dst;
            size_t base;
            if (OUT == 0) {
                dst = Cout;
                base = (size_t)m * HID_ + n0;
            } else {
                int b_ = m >> 11, s_ = m & (S_ - 1), h = blockIdx.x;
                dst = (OUT == 1) ? g_q : (OUT == 2) ? g_k : g_v;
                base = (((size_t)b_ * H_ + h) * S_ + s_) * D_;
            }
#pragma unroll
            for (int nt = 0; nt < 8; nt++) {
                int col = wn * 64 + nt * 8 + qcol;
                *(float2*)(dst + base + col) =
                    make_float2(acc[mt][nt][half * 2], acc[mt][nt][half * 2 + 1]);
            }
        }
    }
}

// ---------------------------------------------------------------------------
// RoPE over Q and K in-place.
// ---------------------------------------------------------------------------
__global__ void rope_kernel(const float* __restrict__ cosb,
                            const float* __restrict__ sinb) {
    int tid = blockIdx.x * 256 + threadIdx.x;
    int d = tid & 63;
    int s = (tid >> 6) & (S_ - 1);
    int bh = tid >> 17;
    size_t base = ((size_t)bh * S_ + s) * D_;
    float c0 = cosb[s * D_ + d], c1 = cosb[s * D_ + d + 64];
    float s0 = sinb[s * D_ + d], s1 = sinb[s * D_ + d + 64];

    float q0 = g_q[base + d], q1 = g_q[base + d + 64];
    g_q[base + d] = q0 * c0 - q1 * s0;
    g_q[base + d + 64] = q1 * c1 + q0 * s1;

    float k0 = g_k[base + d], k1 = g_k[base + d + 64];
    g_k[base + d] = k0 * c0 - k1 * s0;
    g_k[base + d + 64] = k1 * c1 + k0 * s1;
}

// ---------------------------------------------------------------------------
// Flash attention, fp32 (unchanged from R1 — known good)
// ---------------------------------------------------------------------------
__global__ __launch_bounds__(256, 1) void attn_kernel() {
    extern __shared__ float sm_[];
    float* Qs = sm_;
    float* Ks = sm_ + 128 * 132;
    float* Vs = sm_ + 2 * 128 * 132;

    const int t = threadIdx.x, tx = t & 15, ty = t >> 4;
    const int bh = blockIdx.y;
    const int q0 = blockIdx.x * 128;
    const float* Qg = g_q + ((size_t)bh * S_ + q0) * D_;
    const float* Kg = g_k + (size_t)bh * S_ * D_;
    const float* Vg = g_v + (size_t)bh * S_ * D_;

#pragma unroll
    for (int i = 0; i < 16; i++) {
        int x = t + i * 256;
        int row = x >> 5;
        int d4 = (x & 31) * 4;
        float4 v = *(const float4*)(Qg + (size_t)row * D_ + d4);
        Qs[(d4 + 0) * 132 + row] = v.x;
        Qs[(d4 + 1) * 132 + row] = v.y;
        Qs[(d4 + 2) * 132 + row] = v.z;
        Qs[(d4 + 3) * 132 + row] = v.w;
    }

    float mI[8], lI[8];
    unsigned long long O2[8][4];
#pragma unroll
    for (int i = 0; i < 8; i++) {
        mI[i] = -1e30f;
        lI[i] = 0.f;
#pragma unroll
        for (int j = 0; j < 4; j++) O2[i][j] = 0ULL;
    }

    const float scale = 0.088388347648318447f;

    for (int kt = 0; kt < S_ / 128; kt++) {
        const float* Kt = Kg + (size_t)kt * 128 * D_;
        const float* Vt = Vg + (size_t)kt * 128 * D_;
        __syncthreads();
#pragma unroll
        for (int i = 0; i < 16; i++) {
            int x = t + i * 256;
            int row = x >> 5;
            int d4 = (x & 31) * 4;
            float4 v = *(const float4*)(Kt + (size_t)row * D_ + d4);
            Ks[(d4 + 0) * 132 + row] = v.x;
            Ks[(d4 + 1) * 132 + row] = v.y;
            Ks[(d4 + 2) * 132 + row] = v.z;
            Ks[(d4 + 3) * 132 + row] = v.w;
            float4 w = *(const float4*)(Vt + (size_t)row * D_ + d4);
            *(float4*)(Vs + (size_t)row * 132 + d4) = w;
        }
        __syncthreads();

        unsigned long long Sa[8][4];
#pragma unroll
        for (int i = 0; i < 8; i++)
#pragma unroll
            for (int j = 0; j < 4; j++) Sa[i][j] = 0ULL;

#pragma unroll 4
        for (int d = 0; d < 128; d++) {
            float4 a0 = *(const float4*)(Qs + d * 132 + ty * 4);
            float4 a1 = *(const float4*)(Qs + d * 132 + ty * 4 + 64);
            ulonglong2 b0 = *(const ulonglong2*)(Ks + d * 132 + tx * 4);
            ulonglong2 b1 = *(const ulonglong2*)(Ks + d * 132 + tx * 4 + 64);
            unsigned long long bb[4] = {b0.x, b0.y, b1.x, b1.y};
            float av[8] = {a0.x, a0.y, a0.z, a0.w, a1.x, a1.y, a1.z, a1.w};
#pragma unroll
            for (int i = 0; i < 8; i++) {
                unsigned long long aa = pack2(av[i], av[i]);
#pragma unroll
                for (int j = 0; j < 4; j++) ffma2(Sa[i][j], aa, bb[j]);
            }
        }

        float P[8][8];
#pragma unroll
        for (int i = 0; i < 8; i++)
#pragma unroll
            for (int j = 0; j < 4; j++) {
                float2 f = unpack2(Sa[i][j]);
                P[i][2 * j] = f.x;
                P[i][2 * j + 1] = f.y;
            }

        __syncthreads();

#pragma unroll
        for (int i = 0; i < 8; i++) {
            float rm = P[i][0];
#pragma unroll
            for (int j = 1; j < 8; j++) rm = fmaxf(rm, P[i][j]);
#pragma unroll
            for (int off = 8; off > 0; off >>= 1)
                rm = fmaxf(rm, __shfl_xor_sync(0xffffffffu, rm, off));
            rm *= scale;
            float mnew = fmaxf(mI[i], rm);
            float alpha = __expf(mI[i] - mnew);
            float rs = 0.f;
#pragma unroll
            for (int j = 0; j < 8; j++) {
                float p = __expf(P[i][j] * scale - mnew);
                P[i][j] = p;
                rs += p;
            }
#pragma unroll
            for (int off = 8; off > 0; off >>= 1)
                rs += __shfl_xor_sync(0xffffffffu, rs, off);
            lI[i] = lI[i] * alpha + rs;
            mI[i] = mnew;
            unsigned long long al2 = pack2(alpha, alpha);
#pragma unroll
            for (int j = 0; j < 4; j++) O2[i][j] = mul2(O2[i][j], al2);
        }

#pragma unroll
        for (int g = 0; g < 2; g++) {
            int mrow = ty * 4 + g * 64;
#pragma unroll
            for (int j = 0; j < 8; j++) {
                int c = (j < 4) ? (tx * 4 + j) : (64 + tx * 4 + (j - 4));
                *(float4*)(Ks + (size_t)c * 132 + mrow) =
                    make_float4(P[g * 4 + 0][j], P[g * 4 + 1][j],
                                P[g * 4 + 2][j], P[g * 4 + 3][j]);
            }
        }
        __syncthreads();

#pragma unroll 4
        for (int c = 0; c < 128; c++) {
            float4 a0 = *(const float4*)(Ks + c * 132 + ty * 4);
            float4 a1 = *(const float4*)(Ks + c * 132 + ty * 4 + 64);
            ulonglong2 b0 = *(const ulonglong2*)(Vs + c * 132 + tx * 4);
            ulonglong2 b1 = *(const ulonglong2*)(Vs + c * 132 + tx * 4 + 64);
            unsigned long long bb[4] = {b0.x, b0.y, b1.x, b1.y};
            float av[8] = {a0.x, a0.y, a0.z, a0.w, a1.x, a1.y, a1.z, a1.w};
#pragma unroll
            for (int i = 0; i < 8; i++) {
                unsigned long long aa = pack2(av[i], av[i]);
#pragma unroll
                for (int j = 0; j < 4; j++) ffma2(O2[i][j], aa, bb[j]);
            }
        }
    }

    const int b_ = bh >> 4, h = bh & 15;
#pragma unroll
    for (int i = 0; i < 8; i++) {
        int lm = (i < 4) ? (ty * 4 + i) : (64 + ty * 4 + (i - 4));
        int srow = q0 + lm;
        float inv = 1.0f / lI[i];
        float c[8];
#pragma unroll
        for (int j = 0; j < 4; j++) {
            float2 f = unpack2(O2[i][j]);
            c[2 * j] = f.x * inv;
            c[2 * j + 1] = f.y * inv;
        }
        size_t base = ((size_t)b_ * S_ + srow) * HID_ + h * D_;
        *(float4*)(g_ao + base + tx * 4) = make_float4(c[0], c[1], c[2], c[3]);
        *(float4*)(g_ao + base + tx * 4 + 64) = make_float4(c[4], c[5], c[6], c[7]);
    }
}

// ---------------------------------------------------------------------------
// Launch
// ---------------------------------------------------------------------------
extern "C" void kernel_launch(void* const* d_in, const int* in_sizes, int n_in,
                              void* d_out, int out_size) {
    const float* X = (const float*)d_in[0];
    const float* cosb = (const float*)d_in[1];
    const float* sinb = (const float*)d_in[2];
    const float* Wq = (const float*)d_in[3];
    const float* Wk = (const float*)d_in[4];
    const float* Wv = (const float*)d_in[5];
    const float* Wo = (const float*)d_in[6];
    float* out = (float*)d_out;

    cudaFuncSetAttribute(mma_gemm<0>, cudaFuncAttributeMaxDynamicSharedMemorySize, GEMM_SMEM);
    cudaFuncSetAttribute(mma_gemm<1>, cudaFuncAttributeMaxDynamicSharedMemorySize, GEMM_SMEM);
    cudaFuncSetAttribute(mma_gemm<2>, cudaFuncAttributeMaxDynamicSharedMemorySize, GEMM_SMEM);
    cudaFuncSetAttribute(mma_gemm<3>, cudaFuncAttributeMaxDynamicSharedMemorySize, GEMM_SMEM);

    const dim3 ggrid(HID_ / 128, M_ / 128);   // (16, 32)
    const dim3 wgrid(64, 64);
    const dim3 wblk(32, 8);

    asplit_kernel<<<(M_ * HID_ / 4) / 256, 256>>>(X);

    wsplit_kernel<<<wgrid, wblk>>>(Wq);
    mma_gemm<1><<<ggrid, 256, GEMM_SMEM>>>(nullptr);
    wsplit_kernel<<<wgrid, wblk>>>(Wk);
    mma_gemm<2><<<ggrid, 256, GEMM_SMEM>>>(nullptr);
    wsplit_kernel<<<wgrid, wblk>>>(Wv);
    mma_gemm<3><<<ggrid, 256, GEMM_SMEM>>>(nullptr);

    rope_kernel<<<(B_ * H_ * S_ * 64) / 256, 256>>>(cosb, sinb);

    const int smem_bytes = 3 * 128 * 132 * (int)sizeof(float);
    cudaFuncSetAttribute(attn_kernel,
                         cudaFuncAttributeMaxDynamicSharedMemorySize, smem_bytes);
    attn_kernel<<<dim3(S_ / 128, B_ * H_), 256, smem_bytes>>>();

    asplit_kernel<<<(M_ * HID_ / 4) / 256, 256>>>(nullptr);   // from g_ao
    wsplit_kernel<<<wgrid, wblk>>>(Wo);
    mma_gemm<0><<<ggrid, 256, GEMM_SMEM>>>(out);
}

// round 4
// speedup vs baseline: 2.2284x; 1.5789x over previous
#include <cuda_runtime.h>
#include <cuda_bf16.h>
#include <cstdint>

// ---------------------------------------------------------------------------
// Problem constants
// ---------------------------------------------------------------------------
#define B_ 2
#define S_ 2048
#define H_ 16
#define D_ 128
#define HID_ 2048
#define M_ (B_ * S_)   // 4096

// Scratch (device globals — allocation-free per harness rules)
__device__ float g_q[(size_t)B_ * H_ * S_ * D_];   // fp32 Q pre-rope [b,h,s,d]
__device__ float g_k[(size_t)B_ * H_ * S_ * D_];   // fp32 K pre-rope
__device__ float g_ao[(size_t)M_ * HID_];          // attn out [b,s,h*D+d]

// bf16 split buffers for GEMMs
__device__ __nv_bfloat16 g_xhi[(size_t)M_ * HID_];
__device__ __nv_bfloat16 g_xlo[(size_t)M_ * HID_];
__device__ __nv_bfloat16 g_bhi[(size_t)HID_ * HID_];
__device__ __nv_bfloat16 g_blo[(size_t)HID_ * HID_];

// bf16 split buffers for attention operands [b,h,s,d]
#define QKV_ELEMS ((size_t)B_ * H_ * S_ * D_)
__device__ __nv_bfloat16 g_qh[QKV_ELEMS];
__device__ __nv_bfloat16 g_ql[QKV_ELEMS];
__device__ __nv_bfloat16 g_kh[QKV_ELEMS];
__device__ __nv_bfloat16 g_kl[QKV_ELEMS];
__device__ __nv_bfloat16 g_vh[QKV_ELEMS];
__device__ __nv_bfloat16 g_vl[QKV_ELEMS];

// ---------------------------------------------------------------------------
// PTX helpers (non-'a' features only)
// ---------------------------------------------------------------------------
__device__ __forceinline__ uint32_t smem_u32(const void* p) {
    uint32_t a;
    asm("{ .reg .u64 t; cvta.to.shared.u64 t, %1; cvt.u32.u64 %0, t; }"
        : "=r"(a) : "l"(p));
    return a;
}
__device__ __forceinline__ void cpa16(uint32_t s, const void* g) {
    asm volatile("cp.async.cg.shared.global [%0], [%1], 16;" :: "r"(s), "l"(g));
}
#define CP_COMMIT() asm volatile("cp.async.commit_group;" ::: "memory")
#define CP_WAIT0()  asm volatile("cp.async.wait_group 0;" ::: "memory")
#define CP_WAIT1()  asm volatile("cp.async.wait_group 1;" ::: "memory")

#define LDSM4(r, addr)                                                        \
    asm volatile("ldmatrix.sync.aligned.m8n8.x4.shared.b16 {%0,%1,%2,%3}, [%4];" \
                 : "=r"((r)[0]), "=r"((r)[1]), "=r"((r)[2]), "=r"((r)[3])     \
                 : "r"(addr))
#define LDSM4T(r, addr)                                                       \
    asm volatile("ldmatrix.sync.aligned.m8n8.x4.trans.shared.b16 {%0,%1,%2,%3}, [%4];" \
                 : "=r"((r)[0]), "=r"((r)[1]), "=r"((r)[2]), "=r"((r)[3])     \
                 : "r"(addr))

#define MMA16816(d, a, b)                                                     \
    asm volatile(                                                             \
        "mma.sync.aligned.m16n8k16.row.col.f32.bf16.bf16.f32 "                \
        "{%0,%1,%2,%3}, {%4,%5,%6,%7}, {%8,%9}, {%0,%1,%2,%3};"               \
        : "+f"((d)[0]), "+f"((d)[1]), "+f"((d)[2]), "+f"((d)[3])              \
        : "r"((a)[0]), "r"((a)[1]), "r"((a)[2]), "r"((a)[3]),                 \
          "r"((b)[0]), "r"((b)[1]))

__device__ __forceinline__ uint32_t packbf2(float lo, float hi) {
    __nv_bfloat162 p = __float22bfloat162_rn(make_float2(lo, hi));
    return *(uint32_t*)&p;
}

// ---------------------------------------------------------------------------
// fp32 -> bf16 hi/lo split
// ---------------------------------------------------------------------------
__device__ __forceinline__ void split1(float x, unsigned short& h, unsigned short& l) {
    __nv_bfloat16 hb = __float2bfloat16(x);
    __nv_bfloat16 lb = __float2bfloat16(x - __bfloat162float(hb));
    h = __bfloat16_as_ushort(hb);
    l = __bfloat16_as_ushort(lb);
}

// Activations: src [M,K] fp32 -> g_xhi/g_xlo. src==nullptr -> g_ao.
__global__ void asplit_kernel(const float* __restrict__ src) {
    const float* s = src ? src : (const float*)g_ao;
    size_t i = (size_t)blockIdx.x * 256 + threadIdx.x;
    float4 v = ((const float4*)s)[i];
    ushort4 h, l;
    split1(v.x, h.x, l.x);
    split1(v.y, h.y, l.y);
    split1(v.z, h.z, l.z);
    split1(v.w, h.w, l.w);
    ((ushort4*)g_xhi)[i] = h;
    ((ushort4*)g_xlo)[i] = l;
}

// Weights: W [K,N] fp32 -> g_bhi/g_blo [N,K] bf16 (transposed)
__global__ void wsplit_kernel(const float* __restrict__ W) {
    __shared__ float ts[32][33];
    const int tx = threadIdx.x, ty = threadIdx.y;
    const int n0 = blockIdx.x * 32, k0 = blockIdx.y * 32;
#pragma unroll
    for (int i = 0; i < 4; i++)
        ts[ty + 8 * i][tx] = W[(size_t)(k0 + ty + 8 * i) * HID_ + n0 + tx];
    __syncthreads();
#pragma unroll
    for (int i = 0; i < 4; i++) {
        int n = n0 + ty + 8 * i;
        int k = k0 + tx;
        float v = ts[tx][ty + 8 * i];
        unsigned short h, l;
        split1(v, h, l);
        g_bhi[(size_t)n * HID_ + k] = __ushort_as_bfloat16(h);
        g_blo[(size_t)n * HID_ + k] = __ushort_as_bfloat16(l);
    }
}

// ---------------------------------------------------------------------------
// mma.sync bf16x3 GEMM (unchanged from R3 except OUT==3 splits V to bf16)
// ---------------------------------------------------------------------------
#define PITCH 144
#define MATB  (128 * PITCH)
#define BUFB  (4 * MATB)
#define GEMM_SMEM (2 * BUFB)

template <int OUT>
__global__ __launch_bounds__(256, 1) void mma_gemm(float* __restrict__ Cout) {
    extern __shared__ char dsm[];
    const uint32_t sb = smem_u32(dsm);
    const int t = threadIdx.x;
    const int lane = t & 31, wid = t >> 5;
    const int wm = wid & 3, wn = wid >> 2;
    const int m0 = blockIdx.y * 128, n0 = blockIdx.x * 128;

    const __nv_bfloat16* __restrict__ AH = g_xhi;
    const __nv_bfloat16* __restrict__ AL = g_xlo;
    const __nv_bfloat16* __restrict__ BH = g_bhi;
    const __nv_bfloat16* __restrict__ BL = g_blo;

    float acc[2][8][4];
#pragma unroll
    for (int i = 0; i < 2; i++)
#pragma unroll
        for (int j = 0; j < 8; j++)
#pragma unroll
            for (int k = 0; k < 4; k++) acc[i][j][k] = 0.f;

    const int lrow = t >> 3;
    const int lch = t & 7;

    {
        const uint32_t base = sb;
#pragma unroll
        for (int j = 0; j < 4; j++) {
            int row = lrow + j * 32;
            uint32_t sa = base + row * PITCH + lch * 16;
            size_t ga = (size_t)(m0 + row) * HID_ + lch * 8;
            size_t gb = (size_t)(n0 + row) * HID_ + lch * 8;
            cpa16(sa, AH + ga);
            cpa16(sa + MATB, AL + ga);
            cpa16(sa + 2 * MATB, BH + gb);
            cpa16(sa + 3 * MATB, BL + gb);
        }
        CP_COMMIT();
    }

    const uint32_t lm_a_off =
        (uint32_t)((wm * 32 + (lane & 15)) * PITCH + (lane >> 4) * 16);
    const uint32_t lm_b_off =
        (uint32_t)((wn * 64 + (lane & 15)) * PITCH + (lane >> 4) * 16);

    for (int c = 0; c < HID_ / 64; c++) {
        CP_WAIT0();
        __syncthreads();

        if (c + 1 < HID_ / 64) {
            const uint32_t base = sb + ((c + 1) & 1) * BUFB;
            const int k0 = (c + 1) * 64;
#pragma unroll
            for (int j = 0; j < 4; j++) {
                int row = lrow + j * 32;
                uint32_t sa = base + row * PITCH + lch * 16;
                size_t ga = (size_t)(m0 + row) * HID_ + k0 + lch * 8;
                size_t gb = (size_t)(n0 + row) * HID_ + k0 + lch * 8;
                cpa16(sa, AH + ga);
                cpa16(sa + MATB, AL + ga);
                cpa16(sa + 2 * MATB, BH + gb);
                cpa16(sa + 3 * MATB, BL + gb);
            }
            CP_COMMIT();
        }

        const uint32_t cb = sb + (c & 1) * BUFB;
#pragma unroll
        for (int ks = 0; ks < 4; ks++) {
            uint32_t ah[2][4], al[2][4];
#pragma unroll
            for (int mt = 0; mt < 2; mt++) {
                uint32_t addr = cb + lm_a_off + mt * (16 * PITCH) + ks * 32;
                LDSM4(ah[mt], addr);
                LDSM4(al[mt], addr + MATB);
            }
            uint32_t bh[8][2], bl[8][2];
#pragma unroll
            for (int np = 0; np < 4; np++) {
                uint32_t addr = cb + 2 * MATB + lm_b_off + np * (16 * PITCH) + ks * 32;
                uint32_t r[4];
                LDSM4(r, addr);
                bh[2 * np][0] = r[0]; bh[2 * np + 1][0] = r[1];
                bh[2 * np][1] = r[2]; bh[2 * np + 1][1] = r[3];
                LDSM4(r, addr + MATB);
                bl[2 * np][0] = r[0]; bl[2 * np + 1][0] = r[1];
                bl[2 * np][1] = r[2]; bl[2 * np + 1][1] = r[3];
            }
#pragma unroll
            for (int mt = 0; mt < 2; mt++)
#pragma unroll
                for (int nt = 0; nt < 8; nt++) {
                    MMA16816(acc[mt][nt], ah[mt], bh[nt]);
                    MMA16816(acc[mt][nt], al[mt], bh[nt]);
                    MMA16816(acc[mt][nt], ah[mt], bl[nt]);
                }
        }
        __syncthreads();
    }

    const int qrow = lane >> 2;
    const int qcol = (lane & 3) * 2;
#pragma unroll
    for (int mt = 0; mt < 2; mt++) {
#pragma unroll
        for (int half = 0; half < 2; half++) {
            const int m = m0 + wm * 32 + mt * 16 + qrow + half * 8;
            if (OUT == 3) {
                // V: split to bf16 hi/lo directly
                int b_ = m >> 11, s_ = m & (S_ - 1), h = blockIdx.x;
                size_t base = (((size_t)b_ * H_ + h) * S_ + s_) * D_;
#pragma unroll
                for (int nt = 0; nt < 8; nt++) {
                    int col = wn * 64 + nt * 8 + qcol;
                    float x = acc[mt][nt][half * 2];
                    float y = acc[mt][nt][half * 2 + 1];
                    unsigned short hx, lx, hy, ly;
                    split1(x, hx, lx);
                    split1(y, hy, ly);
                    *(uint32_t*)(g_vh + base + col) = (uint32_t)hx | ((uint32_t)hy << 16);
                    *(uint32_t*)(g_vl + base + col) = (uint32_t)lx | ((uint32_t)ly << 16);
                }
            } else {
                float* dst;
                size_t base;
                if (OUT == 0) {
                    dst = Cout;
                    base = (size_t)m * HID_ + n0;
                } else {
                    int b_ = m >> 11, s_ = m & (S_ - 1), h = blockIdx.x;
                    dst = (OUT == 1) ? g_q : g_k;
                    base = (((size_t)b_ * H_ + h) * S_ + s_) * D_;
                }
#pragma unroll
                for (int nt = 0; nt < 8; nt++) {
                    int col = wn * 64 + nt * 8 + qcol;
                    *(float2*)(dst + base + col) =
                        make_float2(acc[mt][nt][half * 2], acc[mt][nt][half * 2 + 1]);
                }
            }
        }
    }
}

// ---------------------------------------------------------------------------
// RoPE: read fp32 g_q/g_k, rotate, split to bf16 hi/lo.
// ---------------------------------------------------------------------------
__global__ void rope_split_kernel(const float* __restrict__ cosb,
                                  const float* __restrict__ sinb) {
    int tid = blockIdx.x * 256 + threadIdx.x;
    int d = tid & 63;
    int s = (tid >> 6) & (S_ - 1);
    int bh = tid >> 17;
    size_t base = ((size_t)bh * S_ + s) * D_;
    float c0 = cosb[s * D_ + d], c1 = cosb[s * D_ + d + 64];
    float s0 = sinb[s * D_ + d], s1 = sinb[s * D_ + d + 64];

    float q0 = g_q[base + d], q1 = g_q[base + d + 64];
    float k0 = g_k[base + d], k1 = g_k[base + d + 64];
    float qa = q0 * c0 - q1 * s0;
    float qb = q1 * c1 + q0 * s1;
    float ka = k0 * c0 - k1 * s0;
    float kb = k1 * c1 + k0 * s1;

    unsigned short h, l;
    split1(qa, h, l);
    g_qh[base + d] = __ushort_as_bfloat16(h);
    g_ql[base + d] = __ushort_as_bfloat16(l);
    split1(qb, h, l);
    g_qh[base + d + 64] = __ushort_as_bfloat16(h);
    g_ql[base + d + 64] = __ushort_as_bfloat16(l);
    split1(ka, h, l);
    g_kh[base + d] = __ushort_as_bfloat16(h);
    g_kl[base + d] = __ushort_as_bfloat16(l);
    split1(kb, h, l);
    g_kh[base + d + 64] = __ushort_as_bfloat16(h);
    g_kl[base + d + 64] = __ushort_as_bfloat16(l);
}

// ---------------------------------------------------------------------------
// Flash attention on mma.sync bf16x3.
// CTA: 128 q-rows of one (b,h); 8 warps, warp owns 16 q-rows x all 128 keys/d.
// SMEM: Qh,Ql,Kh,Kl,Vh,Vl each [128 rows][128 bf16] at 272B pitch = 204KB.
// P kept in registers (S C-frag == PV A-frag layout).
// ---------------------------------------------------------------------------
#define AP   272
#define AMAT (128 * AP)               // 34816
#define ATTN_SMEM (6 * AMAT)          // 208896

__global__ __launch_bounds__(256, 1) void attn_mma_kernel() {
    extern __shared__ char sm8[];
    const uint32_t sb = smem_u32(sm8);
    const uint32_t Qh = sb,            Ql = sb + AMAT;
    const uint32_t Kh = sb + 2 * AMAT, Kl = sb + 3 * AMAT;
    const uint32_t Vh = sb + 4 * AMAT, Vl = sb + 5 * AMAT;

    const int t = threadIdx.x, lane = t & 31, wid = t >> 5;
    const int bh = blockIdx.y;
    const int q0 = blockIdx.x * 128;
    const size_t qoff = ((size_t)bh * S_ + q0) * D_;
    const size_t koff = (size_t)bh * S_ * D_;

    // Q tile load (one group)
#pragma unroll
    for (int j = 0; j < 8; j++) {
        int idx = t + j * 256;               // 0..2047
        int row = idx >> 4, ch = idx & 15;
        uint32_t so = (uint32_t)(row * AP + ch * 16);
        size_t go = qoff + (size_t)row * D_ + ch * 8;
        cpa16(Qh + so, g_qh + go);
        cpa16(Ql + so, g_ql + go);
    }
    CP_COMMIT();

    float sa[16][4];                         // S / P fragments
    float oa[16][4];                         // O accumulators
#pragma unroll
    for (int i = 0; i < 16; i++)
#pragma unroll
        for (int j = 0; j < 4; j++) oa[i][j] = 0.f;
    float m0r = -1e30f, m1r = -1e30f, l0r = 0.f, l1r = 0.f;

    const float scale = 0.088388347648318447f;   // 1/sqrt(128)
    const uint32_t a_off =
        (uint32_t)((wid * 16 + (lane & 15)) * AP + (lane >> 4) * 16);
    const uint32_t lm_lo = (uint32_t)((lane & 15) * AP + (lane >> 4) * 16);

    for (int kt = 0; kt < S_ / 128; kt++) {
        __syncthreads();                     // SMEM reuse fence
        // K group
#pragma unroll
        for (int j = 0; j < 8; j++) {
            int idx = t + j * 256;
            int row = idx >> 4, ch = idx & 15;
            uint32_t so = (uint32_t)(row * AP + ch * 16);
            size_t go = koff + (size_t)(kt * 128 + row) * D_ + ch * 8;
            cpa16(Kh + so, g_kh + go);
            cpa16(Kl + so, g_kl + go);
        }
        CP_COMMIT();
        // V group
#pragma unroll
        for (int j = 0; j < 8; j++) {
            int idx = t + j * 256;
            int row = idx >> 4, ch = idx & 15;
            uint32_t so = (uint32_t)(row * AP + ch * 16);
            size_t go = koff + (size_t)(kt * 128 + row) * D_ + ch * 8;
            cpa16(Vh + so, g_vh + go);
            cpa16(Vl + so, g_vl + go);
        }
        CP_COMMIT();

        CP_WAIT1();                          // Q (+K) ready; V may be in flight
        __syncthreads();

        // ---- S = Q K^T (3-term) ----
#pragma unroll
        for (int i = 0; i < 16; i++)
#pragma unroll
            for (int j = 0; j < 4; j++) sa[i][j] = 0.f;

#pragma unroll
        for (int ks = 0; ks < 8; ks++) {
            uint32_t qh[4], ql[4];
            LDSM4(qh, Qh + a_off + ks * 32);
            LDSM4(ql, Ql + a_off + ks * 32);
#pragma unroll
            for (int np = 0; np < 8; np++) {
                uint32_t boff = lm_lo + (uint32_t)(np * 16 * AP) + ks * 32;
                uint32_t r[4], kh0[2], kh1[2], kl0[2], kl1[2];
                LDSM4(r, Kh + boff);
                kh0[0] = r[0]; kh1[0] = r[1]; kh0[1] = r[2]; kh1[1] = r[3];
                LDSM4(r, Kl + boff);
                kl0[0] = r[0]; kl1[0] = r[1]; kl0[1] = r[2]; kl1[1] = r[3];
                MMA16816(sa[2 * np], qh, kh0);
                MMA16816(sa[2 * np], ql, kh0);
                MMA16816(sa[2 * np], qh, kl0);
                MMA16816(sa[2 * np + 1], qh, kh1);
                MMA16816(sa[2 * np + 1], ql, kh1);
                MMA16816(sa[2 * np + 1], qh, kl1);
            }
        }

        // ---- online softmax (rows qrow, qrow+8 per thread) ----
        float rm0 = -1e30f, rm1 = -1e30f;
#pragma unroll
        for (int nt = 0; nt < 16; nt++) {
            rm0 = fmaxf(rm0, fmaxf(sa[nt][0], sa[nt][1]));
            rm1 = fmaxf(rm1, fmaxf(sa[nt][2], sa[nt][3]));
        }
#pragma unroll
        for (int off = 1; off <= 2; off <<= 1) {
            rm0 = fmaxf(rm0, __shfl_xor_sync(0xffffffffu, rm0, off));
            rm1 = fmaxf(rm1, __shfl_xor_sync(0xffffffffu, rm1, off));
        }
        float mn0 = fmaxf(m0r, rm0 * scale);
        float mn1 = fmaxf(m1r, rm1 * scale);
        float al0 = __expf(m0r - mn0);
        float al1 = __expf(m1r - mn1);
        m0r = mn0;
        m1r = mn1;
        float rs0 = 0.f, rs1 = 0.f;
#pragma unroll
        for (int nt = 0; nt < 16; nt++) {
            float p0 = __expf(fmaf(sa[nt][0], scale, -mn0));
            float p1 = __expf(fmaf(sa[nt][1], scale, -mn0));
            float p2 = __expf(fmaf(sa[nt][2], scale, -mn1));
            float p3 = __expf(fmaf(sa[nt][3], scale, -mn1));
            sa[nt][0] = p0; sa[nt][1] = p1; sa[nt][2] = p2; sa[nt][3] = p3;
            rs0 += p0 + p1;
            rs1 += p2 + p3;
        }
#pragma unroll
        for (int off = 1; off <= 2; off <<= 1) {
            rs0 += __shfl_xor_sync(0xffffffffu, rs0, off);
            rs1 += __shfl_xor_sync(0xffffffffu, rs1, off);
        }
        l0r = l0r * al0 + rs0;
        l1r = l1r * al1 + rs1;
#pragma unroll
        for (int nt = 0; nt < 16; nt++) {
            oa[nt][0] *= al0;
            oa[nt][1] *= al0;
            oa[nt][2] *= al1;
            oa[nt][3] *= al1;
        }

        CP_WAIT0();                          // V ready
        __syncthreads();

        // ---- O += P V (3-term), P converted in registers ----
#pragma unroll
        for (int ks = 0; ks < 8; ks++) {
            uint32_t aH[4], aL[4];
#pragma unroll
            for (int g = 0; g < 2; g++) {    // tiles 2ks, 2ks+1
                const int tt = 2 * ks + g;
                float x0 = sa[tt][0], y0 = sa[tt][1];
                float x1 = sa[tt][2], y1 = sa[tt][3];
                uint32_t h0 = packbf2(x0, y0);
                uint32_t h1 = packbf2(x1, y1);
                float x0r = x0 - __uint_as_float(h0 << 16);
                float y0r = y0 - __uint_as_float(h0 & 0xffff0000u);
                float x1r = x1 - __uint_as_float(h1 << 16);
                float y1r = y1 - __uint_as_float(h1 & 0xffff0000u);
                aH[2 * g]     = h0;
                aH[2 * g + 1] = h1;
                aL[2 * g]     = packbf2(x0r, y0r);
                aL[2 * g + 1] = packbf2(x1r, y1r);
            }
            const uint32_t vbase = lm_lo + (uint32_t)(ks * 16 * AP);
#pragma unroll
            for (int np = 0; np < 8; np++) {
                uint32_t r[4], vh0[2], vh1[2], vl0[2], vl1[2];
                LDSM4T(r, Vh + vbase + np * 32);
                vh0[0] = r[0]; vh0[1] = r[1]; vh1[0] = r[2]; vh1[1] = r[3];
                LDSM4T(r, Vl + vbase + np * 32);
                vl0[0] = r[0]; vl0[1] = r[1]; vl1[0] = r[2]; vl1[1] = r[3];
                MMA16816(oa[2 * np], aH, vh0);
                MMA16816(oa[2 * np], aL, vh0);
                MMA16816(oa[2 * np], aH, vl0);
                MMA16816(oa[2 * np + 1], aH, vh1);
                MMA16816(oa[2 * np + 1], aL, vh1);
                MMA16816(oa[2 * np + 1], aH, vl1);
            }
        }
    }

    // ---- finalize ----
    const int b_ = bh >> 4, h = bh & 15;
    const int row0 = q0 + wid * 16 + (lane >> 2);
    const float inv0 = 1.0f / l0r, inv1 = 1.0f / l1r;
    const size_t base0 = ((size_t)b_ * S_ + row0) * HID_ + h * D_;
    const size_t base1 = ((size_t)b_ * S_ + row0 + 8) * HID_ + h * D_;
    const int col0 = (lane & 3) * 2;
#pragma unroll
    for (int nt = 0; nt < 16; nt++) {
        int col = 8 * nt + col0;
        *(float2*)(g_ao + base0 + col) = make_float2(oa[nt][0] * inv0, oa[nt][1] * inv0);
        *(float2*)(g_ao + base1 + col) = make_float2(oa[nt][2] * inv1, oa[nt][3] * inv1);
    }
}

// ---------------------------------------------------------------------------
// Launch
// ---------------------------------------------------------------------------
extern "C" void kernel_launch(void* const* d_in, const int* in_sizes, int n_in,
                              void* d_out, int out_size) {
    const float* X = (const float*)d_in[0];
    const float* cosb = (const float*)d_in[1];
    const float* sinb = (const float*)d_in[2];
    const float* Wq = (const float*)d_in[3];
    const float* Wk = (const float*)d_in[4];
    const float* Wv = (const float*)d_in[5];
    const float* Wo = (const float*)d_in[6];
    float* out = (float*)d_out;

    cudaFuncSetAttribute(mma_gemm<0>, cudaFuncAttributeMaxDynamicSharedMemorySize, GEMM_SMEM);
    cudaFuncSetAttribute(mma_gemm<1>, cudaFuncAttributeMaxDynamicSharedMemorySize, GEMM_SMEM);
    cudaFuncSetAttribute(mma_gemm<2>, cudaFuncAttributeMaxDynamicSharedMemorySize, GEMM_SMEM);
    cudaFuncSetAttribute(mma_gemm<3>, cudaFuncAttributeMaxDynamicSharedMemorySize, GEMM_SMEM);
    cudaFuncSetAttribute(attn_mma_kernel, cudaFuncAttributeMaxDynamicSharedMemorySize, ATTN_SMEM);

    const dim3 ggrid(HID_ / 128, M_ / 128);   // (16, 32)
    const dim3 wgrid(64, 64);
    const dim3 wblk(32, 8);

    asplit_kernel<<<(M_ * HID_ / 4) / 256, 256>>>(X);

    wsplit_kernel<<<wgrid, wblk>>>(Wq);
    mma_gemm<1><<<ggrid, 256, GEMM_SMEM>>>(nullptr);
    wsplit_kernel<<<wgrid, wblk>>>(Wk);
    mma_gemm<2><<<ggrid, 256, GEMM_SMEM>>>(nullptr);
    wsplit_kernel<<<wgrid, wblk>>>(Wv);
    mma_gemm<3><<<ggrid, 256, GEMM_SMEM>>>(nullptr);

    rope_split_kernel<<<(B_ * H_ * S_ * 64) / 256, 256>>>(cosb, sinb);

    attn_mma_kernel<<<dim3(S_ / 128, B_ * H_), 256, ATTN_SMEM>>>();

    asplit_kernel<<<(M_ * HID_ / 4) / 256, 256>>>(nullptr);   // from g_ao
    wsplit_kernel<<<wgrid, wblk>>>(Wo);
    mma_gemm<0><<<ggrid, 256, GEMM_SMEM>>>(out);
}

// round 5
// speedup vs baseline: 2.3572x; 1.0578x over previous
#include <cuda_runtime.h>
#include <cuda_bf16.h>
#include <cstdint>

// ---------------------------------------------------------------------------
// Problem constants
// ---------------------------------------------------------------------------
#define B_ 2
#define S_ 2048
#define H_ 16
#define D_ 128
#define HID_ 2048
#define M_ (B_ * S_)   // 4096

// Scratch (device globals — allocation-free per harness rules)
__device__ float g_q[(size_t)B_ * H_ * S_ * D_];   // fp32 Q pre-rope [b,h,s,d]
__device__ float g_k[(size_t)B_ * H_ * S_ * D_];   // fp32 K pre-rope
__device__ float g_ao[(size_t)M_ * HID_];          // attn out [b,s,h*D+d]

// bf16 split buffers for GEMMs. Weights: 4 matrices, [N][K] transposed.
__device__ __nv_bfloat16 g_xhi[(size_t)M_ * HID_];
__device__ __nv_bfloat16 g_xlo[(size_t)M_ * HID_];
__device__ __nv_bfloat16 g_bhi[(size_t)4 * HID_ * HID_];
__device__ __nv_bfloat16 g_blo[(size_t)4 * HID_ * HID_];

// bf16 split buffers for attention operands [b,h,s,d]
#define QKV_ELEMS ((size_t)B_ * H_ * S_ * D_)
__device__ __nv_bfloat16 g_qh[QKV_ELEMS];
__device__ __nv_bfloat16 g_ql[QKV_ELEMS];
__device__ __nv_bfloat16 g_kh[QKV_ELEMS];
__device__ __nv_bfloat16 g_kl[QKV_ELEMS];
__device__ __nv_bfloat16 g_vh[QKV_ELEMS];
__device__ __nv_bfloat16 g_vl[QKV_ELEMS];

// ---------------------------------------------------------------------------
// PTX helpers (non-'a' features only)
// ---------------------------------------------------------------------------
__device__ __forceinline__ uint32_t smem_u32(const void* p) {
    uint32_t a;
    asm("{ .reg .u64 t; cvta.to.shared.u64 t, %1; cvt.u32.u64 %0, t; }"
        : "=r"(a) : "l"(p));
    return a;
}
__device__ __forceinline__ void cpa16(uint32_t s, const void* g) {
    asm volatile("cp.async.cg.shared.global [%0], [%1], 16;" :: "r"(s), "l"(g));
}
#define CP_COMMIT() asm volatile("cp.async.commit_group;" ::: "memory")
#define CP_WAIT0()  asm volatile("cp.async.wait_group 0;" ::: "memory")
#define CP_WAIT1()  asm volatile("cp.async.wait_group 1;" ::: "memory")

#define LDSM4(r, addr)                                                        \
    asm volatile("ldmatrix.sync.aligned.m8n8.x4.shared.b16 {%0,%1,%2,%3}, [%4];" \
                 : "=r"((r)[0]), "=r"((r)[1]), "=r"((r)[2]), "=r"((r)[3])     \
                 : "r"(addr))
#define LDSM4T(r, addr)                                                       \
    asm volatile("ldmatrix.sync.aligned.m8n8.x4.trans.shared.b16 {%0,%1,%2,%3}, [%4];" \
                 : "=r"((r)[0]), "=r"((r)[1]), "=r"((r)[2]), "=r"((r)[3])     \
                 : "r"(addr))

#define MMA16816(d, a, b)                                                     \
    asm volatile(                                                             \
        "mma.sync.aligned.m16n8k16.row.col.f32.bf16.bf16.f32 "                \
        "{%0,%1,%2,%3}, {%4,%5,%6,%7}, {%8,%9}, {%0,%1,%2,%3};"               \
        : "+f"((d)[0]), "+f"((d)[1]), "+f"((d)[2]), "+f"((d)[3])              \
        : "r"((a)[0]), "r"((a)[1]), "r"((a)[2]), "r"((a)[3]),                 \
          "r"((b)[0]), "r"((b)[1]))

__device__ __forceinline__ uint32_t packbf2(float lo, float hi) {
    __nv_bfloat162 p = __float22bfloat162_rn(make_float2(lo, hi));
    return *(uint32_t*)&p;
}

// ---------------------------------------------------------------------------
// fp32 -> bf16 hi/lo split
// ---------------------------------------------------------------------------
__device__ __forceinline__ void split1(float x, unsigned short& h, unsigned short& l) {
    __nv_bfloat16 hb = __float2bfloat16(x);
    __nv_bfloat16 lb = __float2bfloat16(x - __bfloat162float(hb));
    h = __bfloat16_as_ushort(hb);
    l = __bfloat16_as_ushort(lb);
}

// Activations: src [M,K] fp32 -> g_xhi/g_xlo. src==nullptr -> g_ao.
__global__ void asplit_kernel(const float* __restrict__ src) {
    const float* s = src ? src : (const float*)g_ao;
    size_t i = (size_t)blockIdx.x * 256 + threadIdx.x;
    float4 v = ((const float4*)s)[i];
    ushort4 h, l;
    split1(v.x, h.x, l.x);
    split1(v.y, h.y, l.y);
    split1(v.z, h.z, l.z);
    split1(v.w, h.w, l.w);
    ((ushort4*)g_xhi)[i] = h;
    ((ushort4*)g_xlo)[i] = l;
}

// Weights: W [K,N] fp32 -> g_bhi/g_blo slot widx, [N,K] bf16 (transposed)
__global__ void wsplit_kernel(const float* __restrict__ W, int widx) {
    __shared__ float ts[32][33];
    const int tx = threadIdx.x, ty = threadIdx.y;
    const int n0 = blockIdx.x * 32, k0 = blockIdx.y * 32;
    __nv_bfloat16* bh = g_bhi + (size_t)widx * HID_ * HID_;
    __nv_bfloat16* bl = g_blo + (size_t)widx * HID_ * HID_;
#pragma unroll
    for (int i = 0; i < 4; i++)
        ts[ty + 8 * i][tx] = W[(size_t)(k0 + ty + 8 * i) * HID_ + n0 + tx];
    __syncthreads();
#pragma unroll
    for (int i = 0; i < 4; i++) {
        int n = n0 + ty + 8 * i;
        int k = k0 + tx;
        float v = ts[tx][ty + 8 * i];
        unsigned short h, l;
        split1(v, h, l);
        bh[(size_t)n * HID_ + k] = __ushort_as_bfloat16(h);
        bl[(size_t)n * HID_ + k] = __ushort_as_bfloat16(l);
    }
}

// ---------------------------------------------------------------------------
// mma.sync bf16x3 GEMM, 3-stage cp.async pipeline, one sync per chunk.
// CTA tile 128x128, BK=64, 256 threads (warp grid 4m x 2n, warp tile 32x64).
// MODE==1: fused QKV. blockIdx.x = widx*16 + head; widx 0->g_q fp32,
//          1->g_k fp32, 2->split to g_vh/g_vl.
// MODE==0: O projection (weight slot 3), write row-major to Cout.
// ---------------------------------------------------------------------------
#define PITCH 144
#define MATB  (128 * PITCH)          // 18432
#define BUFB  (4 * MATB)             // 73728
#define GEMM_SMEM (3 * BUFB)         // 221184
#define NCH (HID_ / 64)              // 32

template <int MODE>
__global__ __launch_bounds__(256, 1) void mma_gemm(float* __restrict__ Cout) {
    extern __shared__ char dsm[];
    const uint32_t sb = smem_u32(dsm);
    const int t = threadIdx.x;
    const int lane = t & 31, wid = t >> 5;
    const int wm = wid & 3, wn = wid >> 2;
    const int m0 = blockIdx.y * 128;
    const int widx = (MODE == 1) ? (blockIdx.x >> 4) : 3;
    const int nblk = (MODE == 1) ? (blockIdx.x & 15) : blockIdx.x;
    const int n0 = nblk * 128;

    const __nv_bfloat16* __restrict__ AH = g_xhi;
    const __nv_bfloat16* __restrict__ AL = g_xlo;
    const __nv_bfloat16* __restrict__ BH = g_bhi + (size_t)widx * HID_ * HID_;
    const __nv_bfloat16* __restrict__ BL = g_blo + (size_t)widx * HID_ * HID_;

    float acc[2][8][4];
#pragma unroll
    for (int i = 0; i < 2; i++)
#pragma unroll
        for (int j = 0; j < 8; j++)
#pragma unroll
            for (int k = 0; k < 4; k++) acc[i][j][k] = 0.f;

    const int lrow = t >> 3;
    const int lch = t & 7;

    // prologue: stages 0,1
#pragma unroll
    for (int s = 0; s < 2; s++) {
        const uint32_t base = sb + s * BUFB;
        const int k0 = s * 64;
#pragma unroll
        for (int j = 0; j < 4; j++) {
            int row = lrow + j * 32;
            uint32_t sa = base + row * PITCH + lch * 16;
            size_t ga = (size_t)(m0 + row) * HID_ + k0 + lch * 8;
            size_t gb = (size_t)(n0 + row) * HID_ + k0 + lch * 8;
            cpa16(sa, AH + ga);
            cpa16(sa + MATB, AL + ga);
            cpa16(sa + 2 * MATB, BH + gb);
            cpa16(sa + 3 * MATB, BL + gb);
        }
        CP_COMMIT();
    }

    const uint32_t lm_a_off =
        (uint32_t)((wm * 32 + (lane & 15)) * PITCH + (lane >> 4) * 16);
    const uint32_t lm_b_off =
        (uint32_t)((wn * 64 + (lane & 15)) * PITCH + (lane >> 4) * 16);

    int bufn = 0;     // buffer index of chunk c (c mod 3)
    int pbuf = 2;     // buffer index of chunk c+2
    for (int c = 0; c < NCH; c++) {
        CP_WAIT1();           // chunk c resident (only c+1 may be outstanding)
        __syncthreads();      // also: all warps done with buf (c+2)%3 contents

        if (c + 2 < NCH) {
            const uint32_t base = sb + pbuf * BUFB;
            const int k0 = (c + 2) * 64;
#pragma unroll
            for (int j = 0; j < 4; j++) {
                int row = lrow + j * 32;
                uint32_t sa = base + row * PITCH + lch * 16;
                size_t ga = (size_t)(m0 + row) * HID_ + k0 + lch * 8;
                size_t gb = (size_t)(n0 + row) * HID_ + k0 + lch * 8;
                cpa16(sa, AH + ga);
                cpa16(sa + MATB, AL + ga);
                cpa16(sa + 2 * MATB, BH + gb);
                cpa16(sa + 3 * MATB, BL + gb);
            }
        }
        CP_COMMIT();          // commit (possibly empty) group every iteration

        const uint32_t cb = sb + bufn * BUFB;
#pragma unroll
        for (int ks = 0; ks < 4; ks++) {
            uint32_t ah[2][4], al[2][4];
#pragma unroll
            for (int mt = 0; mt < 2; mt++) {
                uint32_t addr = cb + lm_a_off + mt * (16 * PITCH) + ks * 32;
                LDSM4(ah[mt], addr);
                LDSM4(al[mt], addr + MATB);
            }
            uint32_t bh[8][2], bl[8][2];
#pragma unroll
            for (int np = 0; np < 4; np++) {
                uint32_t addr = cb + 2 * MATB + lm_b_off + np * (16 * PITCH) + ks * 32;
                uint32_t r[4];
                LDSM4(r, addr);
                bh[2 * np][0] = r[0]; bh[2 * np + 1][0] = r[1];
                bh[2 * np][1] = r[2]; bh[2 * np + 1][1] = r[3];
                LDSM4(r, addr + MATB);
                bl[2 * np][0] = r[0]; bl[2 * np + 1][0] = r[1];
                bl[2 * np][1] = r[2]; bl[2 * np + 1][1] = r[3];
            }
#pragma unroll
            for (int mt = 0; mt < 2; mt++)
#pragma unroll
                for (int nt = 0; nt < 8; nt++) {
                    MMA16816(acc[mt][nt], ah[mt], bh[nt]);
                    MMA16816(acc[mt][nt], al[mt], bh[nt]);
                    MMA16816(acc[mt][nt], ah[mt], bl[nt]);
                }
        }
        bufn = (bufn == 2) ? 0 : bufn + 1;
        pbuf = (pbuf == 2) ? 0 : pbuf + 1;
    }

    // Epilogue
    const int qrow = lane >> 2;
    const int qcol = (lane & 3) * 2;
#pragma unroll
    for (int mt = 0; mt < 2; mt++) {
#pragma unroll
        for (int half = 0; half < 2; half++) {
            const int m = m0 + wm * 32 + mt * 16 + qrow + half * 8;
            if (MODE == 1 && widx == 2) {
                // V: split to bf16 hi/lo directly
                int b_ = m >> 11, s_ = m & (S_ - 1);
                size_t base = (((size_t)b_ * H_ + nblk) * S_ + s_) * D_;
#pragma unroll
                for (int nt = 0; nt < 8; nt++) {
                    int col = wn * 64 + nt * 8 + qcol;
                    float x = acc[mt][nt][half * 2];
                    float y = acc[mt][nt][half * 2 + 1];
                    unsigned short hx, lx, hy, ly;
                    split1(x, hx, lx);
                    split1(y, hy, ly);
                    *(uint32_t*)(g_vh + base + col) = (uint32_t)hx | ((uint32_t)hy << 16);
                    *(uint32_t*)(g_vl + base + col) = (uint32_t)lx | ((uint32_t)ly << 16);
                }
            } else {
                float* dst;
                size_t base;
                if (MODE == 0) {
                    dst = Cout;
                    base = (size_t)m * HID_ + n0;
                } else {
                    int b_ = m >> 11, s_ = m & (S_ - 1);
                    dst = (widx == 0) ? g_q : g_k;
                    base = (((size_t)b_ * H_ + nblk) * S_ + s_) * D_;
                }
#pragma unroll
                for (int nt = 0; nt < 8; nt++) {
                    int col = wn * 64 + nt * 8 + qcol;
                    *(float2*)(dst + base + col) =
                        make_float2(acc[mt][nt][half * 2], acc[mt][nt][half * 2 + 1]);
                }
            }
        }
    }
}

// ---------------------------------------------------------------------------
// RoPE: read fp32 g_q/g_k, rotate, split to bf16 hi/lo.
// ---------------------------------------------------------------------------
__global__ void rope_split_kernel(const float* __restrict__ cosb,
                                  const float* __restrict__ sinb) {
    int tid = blockIdx.x * 256 + threadIdx.x;
    int d = tid & 63;
    int s = (tid >> 6) & (S_ - 1);
    int bh = tid >> 17;
    size_t base = ((size_t)bh * S_ + s) * D_;
    float c0 = cosb[s * D_ + d], c1 = cosb[s * D_ + d + 64];
    float s0 = sinb[s * D_ + d], s1 = sinb[s * D_ + d + 64];

    float q0 = g_q[base + d], q1 = g_q[base + d + 64];
    float k0 = g_k[base + d], k1 = g_k[base + d + 64];
    float qa = q0 * c0 - q1 * s0;
    float qb = q1 * c1 + q0 * s1;
    float ka = k0 * c0 - k1 * s0;
    float kb = k1 * c1 + k0 * s1;

    unsigned short h, l;
    split1(qa, h, l);
    g_qh[base + d] = __ushort_as_bfloat16(h);
    g_ql[base + d] = __ushort_as_bfloat16(l);
    split1(qb, h, l);
    g_qh[base + d + 64] = __ushort_as_bfloat16(h);
    g_ql[base + d + 64] = __ushort_as_bfloat16(l);
    split1(ka, h, l);
    g_kh[base + d] = __ushort_as_bfloat16(h);
    g_kl[base + d] = __ushort_as_bfloat16(l);
    split1(kb, h, l);
    g_kh[base + d + 64] = __ushort_as_bfloat16(h);
    g_kl[base + d + 64] = __ushort_as_bfloat16(l);
}

// ---------------------------------------------------------------------------
// Flash attention on mma.sync bf16x3 (unchanged from R4 — known good)
// ---------------------------------------------------------------------------
#define AP   272
#define AMAT (128 * AP)               // 34816
#define ATTN_SMEM (6 * AMAT)          // 208896

__global__ __launch_bounds__(256, 1) void attn_mma_kernel() {
    extern __shared__ char sm8[];
    const uint32_t sb = smem_u32(sm8);
    const uint32_t Qh = sb,            Ql = sb + AMAT;
    const uint32_t Kh = sb + 2 * AMAT, Kl = sb + 3 * AMAT;
    const uint32_t Vh = sb + 4 * AMAT, Vl = sb + 5 * AMAT;

    const int t = threadIdx.x, lane = t & 31, wid = t >> 5;
    const int bh = blockIdx.y;
    const int q0 = blockIdx.x * 128;
    const size_t qoff = ((size_t)bh * S_ + q0) * D_;
    const size_t koff = (size_t)bh * S_ * D_;

#pragma unroll
    for (int j = 0; j < 8; j++) {
        int idx = t + j * 256;
        int row = idx >> 4, ch = idx & 15;
        uint32_t so = (uint32_t)(row * AP + ch * 16);
        size_t go = qoff + (size_t)row * D_ + ch * 8;
        cpa16(Qh + so, g_qh + go);
        cpa16(Ql + so, g_ql + go);
    }
    CP_COMMIT();

    float sa[16][4];
    float oa[16][4];
#pragma unroll
    for (int i = 0; i < 16; i++)
#pragma unroll
        for (int j = 0; j < 4; j++) oa[i][j] = 0.f;
    float m0r = -1e30f, m1r = -1e30f, l0r = 0.f, l1r = 0.f;

    const float scale = 0.088388347648318447f;
    const uint32_t a_off =
        (uint32_t)((wid * 16 + (lane & 15)) * AP + (lane >> 4) * 16);
    const uint32_t lm_lo = (uint32_t)((lane & 15) * AP + (lane >> 4) * 16);

    for (int kt = 0; kt < S_ / 128; kt++) {
        __syncthreads();
#pragma unroll
        for (int j = 0; j < 8; j++) {
            int idx = t + j * 256;
            int row = idx >> 4, ch = idx & 15;
            uint32_t so = (uint32_t)(row * AP + ch * 16);
            size_t go = koff + (size_t)(kt * 128 + row) * D_ + ch * 8;
            cpa16(Kh + so, g_kh + go);
            cpa16(Kl + so, g_kl + go);
        }
        CP_COMMIT();
#pragma unroll
        for (int j = 0; j < 8; j++) {
            int idx = t + j * 256;
            int row = idx >> 4, ch = idx & 15;
            uint32_t so = (uint32_t)(row * AP + ch * 16);
            size_t go = koff + (size_t)(kt * 128 + row) * D_ + ch * 8;
            cpa16(Vh + so, g_vh + go);
            cpa16(Vl + so, g_vl + go);
        }
        CP_COMMIT();

        CP_WAIT1();
        __syncthreads();

#pragma unroll
        for (int i = 0; i < 16; i++)
#pragma unroll
            for (int j = 0; j < 4; j++) sa[i][j] = 0.f;

#pragma unroll
        for (int ks = 0; ks < 8; ks++) {
            uint32_t qh[4], ql[4];
            LDSM4(qh, Qh + a_off + ks * 32);
            LDSM4(ql, Ql + a_off + ks * 32);
#pragma unroll
            for (int np = 0; np < 8; np++) {
                uint32_t boff = lm_lo + (uint32_t)(np * 16 * AP) + ks * 32;
                uint32_t r[4], kh0[2], kh1[2], kl0[2], kl1[2];
                LDSM4(r, Kh + boff);
                kh0[0] = r[0]; kh1[0] = r[1]; kh0[1] = r[2]; kh1[1] = r[3];
                LDSM4(r, Kl + boff);
                kl0[0] = r[0]; kl1[0] = r[1]; kl0[1] = r[2]; kl1[1] = r[3];
                MMA16816(sa[2 * np], qh, kh0);
                MMA16816(sa[2 * np], ql, kh0);
                MMA16816(sa[2 * np], qh, kl0);
                MMA16816(sa[2 * np + 1], qh, kh1);
                MMA16816(sa[2 * np + 1], ql, kh1);
                MMA16816(sa[2 * np + 1], qh, kl1);
            }
        }

        float rm0 = -1e30f, rm1 = -1e30f;
#pragma unroll
        for (int nt = 0; nt < 16; nt++) {
            rm0 = fmaxf(rm0, fmaxf(sa[nt][0], sa[nt][1]));
            rm1 = fmaxf(rm1, fmaxf(sa[nt][2], sa[nt][3]));
        }
#pragma unroll
        for (int off = 1; off <= 2; off <<= 1) {
            rm0 = fmaxf(rm0, __shfl_xor_sync(0xffffffffu, rm0, off));
            rm1 = fmaxf(rm1, __shfl_xor_sync(0xffffffffu, rm1, off));
        }
        float mn0 = fmaxf(m0r, rm0 * scale);
        float mn1 = fmaxf(m1r, rm1 * scale);
        float al0 = __expf(m0r - mn0);
        float al1 = __expf(m1r - mn1);
        m0r = mn0;
        m1r = mn1;
        float rs0 = 0.f, rs1 = 0.f;
#pragma unroll
        for (int nt = 0; nt < 16; nt++) {
            float p0 = __expf(fmaf(sa[nt][0], scale, -mn0));
            float p1 = __expf(fmaf(sa[nt][1], scale, -mn0));
            float p2 = __expf(fmaf(sa[nt][2], scale, -mn1));
            float p3 = __expf(fmaf(sa[nt][3], scale, -mn1));
            sa[nt][0] = p0; sa[nt][1] = p1; sa[nt][2] = p2; sa[nt][3] = p3;
            rs0 += p0 + p1;
            rs1 += p2 + p3;
        }
#pragma unroll
        for (int off = 1; off <= 2; off <<= 1) {
            rs0 += __shfl_xor_sync(0xffffffffu, rs0, off);
            rs1 += __shfl_xor_sync(0xffffffffu, rs1, off);
        }
        l0r = l0r * al0 + rs0;
        l1r = l1r * al1 + rs1;
#pragma unroll
        for (int nt = 0; nt < 16; nt++) {
            oa[nt][0] *= al0;
            oa[nt][1] *= al0;
            oa[nt][2] *= al1;
            oa[nt][3] *= al1;
        }

        CP_WAIT0();
        __syncthreads();

#pragma unroll
        for (int ks = 0; ks < 8; ks++) {
            uint32_t aH[4], aL[4];
#pragma unroll
            for (int g = 0; g < 2; g++) {
                const int tt = 2 * ks + g;
                float x0 = sa[tt][0], y0 = sa[tt][1];
                float x1 = sa[tt][2], y1 = sa[tt][3];
                uint32_t h0 = packbf2(x0, y0);
                uint32_t h1 = packbf2(x1, y1);
                float x0r = x0 - __uint_as_float(h0 << 16);
                float y0r = y0 - __uint_as_float(h0 & 0xffff0000u);
                float x1r = x1 - __uint_as_float(h1 << 16);
                float y1r = y1 - __uint_as_float(h1 & 0xffff0000u);
                aH[2 * g]     = h0;
                aH[2 * g + 1] = h1;
                aL[2 * g]     = packbf2(x0r, y0r);
                aL[2 * g + 1] = packbf2(x1r, y1r);
            }
            const uint32_t vbase = lm_lo + (uint32_t)(ks * 16 * AP);
#pragma unroll
            for (int np = 0; np < 8; np++) {
                uint32_t r[4], vh0[2], vh1[2], vl0[2], vl1[2];
                LDSM4T(r, Vh + vbase + np * 32);
                vh0[0] = r[0]; vh0[1] = r[1]; vh1[0] = r[2]; vh1[1] = r[3];
                LDSM4T(r, Vl + vbase + np * 32);
                vl0[0] = r[0]; vl0[1] = r[1]; vl1[0] = r[2]; vl1[1] = r[3];
                MMA16816(oa[2 * np], aH, vh0);
                MMA16816(oa[2 * np], aL, vh0);
                MMA16816(oa[2 * np], aH, vl0);
                MMA16816(oa[2 * np + 1], aH, vh1);
                MMA16816(oa[2 * np + 1], aL, vh1);
                MMA16816(oa[2 * np + 1], aH, vl1);
            }
        }
    }

    const int b_ = bh >> 4, h = bh & 15;
    const int row0 = q0 + wid * 16 + (lane >> 2);
    const float inv0 = 1.0f / l0r, inv1 = 1.0f / l1r;
    const size_t base0 = ((size_t)b_ * S_ + row0) * HID_ + h * D_;
    const size_t base1 = ((size_t)b_ * S_ + row0 + 8) * HID_ + h * D_;
    const int col0 = (lane & 3) * 2;
#pragma unroll
    for (int nt = 0; nt < 16; nt++) {
        int col = 8 * nt + col0;
        *(float2*)(g_ao + base0 + col) = make_float2(oa[nt][0] * inv0, oa[nt][1] * inv0);
        *(float2*)(g_ao + base1 + col) = make_float2(oa[nt][2] * inv1, oa[nt][3] * inv1);
    }
}

// ---------------------------------------------------------------------------
// Launch
// ---------------------------------------------------------------------------
extern "C" void kernel_launch(void* const* d_in, const int* in_sizes, int n_in,
                              void* d_out, int out_size) {
    const float* X = (const float*)d_in[0];
    const float* cosb = (const float*)d_in[1];
    const float* sinb = (const float*)d_in[2];
    const float* Wq = (const float*)d_in[3];
    const float* Wk = (const float*)d_in[4];
    const float* Wv = (const float*)d_in[5];
    const float* Wo = (const float*)d_in[6];
    float* out = (float*)d_out;

    cudaFuncSetAttribute(mma_gemm<0>, cudaFuncAttributeMaxDynamicSharedMemorySize, GEMM_SMEM);
    cudaFuncSetAttribute(mma_gemm<1>, cudaFuncAttributeMaxDynamicSharedMemorySize, GEMM_SMEM);
    cudaFuncSetAttribute(attn_mma_kernel, cudaFuncAttributeMaxDynamicSharedMemorySize, ATTN_SMEM);

    const dim3 wgrid(64, 64);
    const dim3 wblk(32, 8);

    // split all weights + activations up front
    wsplit_kernel<<<wgrid, wblk>>>(Wq, 0);
    wsplit_kernel<<<wgrid, wblk>>>(Wk, 1);
    wsplit_kernel<<<wgrid, wblk>>>(Wv, 2);
    wsplit_kernel<<<wgrid, wblk>>>(Wo, 3);
    asplit_kernel<<<(M_ * HID_ / 4) / 256, 256>>>(X);

    // fused QKV projection: grid.x = 3 weights x 16 head-tiles
    mma_gemm<1><<<dim3(48, M_ / 128), 256, GEMM_SMEM>>>(nullptr);

    rope_split_kernel<<<(B_ * H_ * S_ * 64) / 256, 256>>>(cosb, sinb);

    attn_mma_kernel<<<dim3(S_ / 128, B_ * H_), 256, ATTN_SMEM>>>();

    asplit_kernel<<<(M_ * HID_ / 4) / 256, 256>>>(nullptr);   // from g_ao
    mma_gemm<0><<<dim3(HID_ / 128, M_ / 128), 256, GEMM_SMEM>>>(out);
}

// round 6
// speedup vs baseline: 2.3586x; 1.0006x over previous
#include <cuda_runtime.h>
#include <cuda_fp16.h>
#include <cstdint>

// ---------------------------------------------------------------------------
// Problem constants
// ---------------------------------------------------------------------------
#define B_ 2
#define S_ 2048
#define H_ 16
#define D_ 128
#define HID_ 2048
#define M_ (B_ * S_)   // 4096

// Scratch (device globals — allocation-free per harness rules)
__device__ float g_q[(size_t)B_ * H_ * S_ * D_];   // fp32 Q pre-rope [b,h,s,d]
__device__ float g_k[(size_t)B_ * H_ * S_ * D_];   // fp32 K pre-rope

// fp16 split buffers for GEMMs. Weights: 4 matrices, [N][K] transposed.
__device__ __half g_xhi[(size_t)M_ * HID_];
__device__ __half g_xlo[(size_t)M_ * HID_];
__device__ __half g_bhi[(size_t)4 * HID_ * HID_];
__device__ __half g_blo[(size_t)4 * HID_ * HID_];

// fp16 split buffers for attention operands [b,h,s,d]
#define QKV_ELEMS ((size_t)B_ * H_ * S_ * D_)
__device__ __half g_qh[QKV_ELEMS];
__device__ __half g_ql[QKV_ELEMS];
__device__ __half g_kh[QKV_ELEMS];
__device__ __half g_kl[QKV_ELEMS];
__device__ __half g_vh[QKV_ELEMS];
__device__ __half g_vl[QKV_ELEMS];

// ---------------------------------------------------------------------------
// PTX helpers (non-'a' features only)
// ---------------------------------------------------------------------------
__device__ __forceinline__ uint32_t smem_u32(const void* p) {
    uint32_t a;
    asm("{ .reg .u64 t; cvta.to.shared.u64 t, %1; cvt.u32.u64 %0, t; }"
        : "=r"(a) : "l"(p));
    return a;
}
__device__ __forceinline__ void cpa16(uint32_t s, const void* g) {
    asm volatile("cp.async.cg.shared.global [%0], [%1], 16;" :: "r"(s), "l"(g));
}
#define CP_COMMIT() asm volatile("cp.async.commit_group;" ::: "memory")
#define CP_WAIT0()  asm volatile("cp.async.wait_group 0;" ::: "memory")
#define CP_WAIT1()  asm volatile("cp.async.wait_group 1;" ::: "memory")

#define LDSM4(r, addr)                                                        \
    asm volatile("ldmatrix.sync.aligned.m8n8.x4.shared.b16 {%0,%1,%2,%3}, [%4];" \
                 : "=r"((r)[0]), "=r"((r)[1]), "=r"((r)[2]), "=r"((r)[3])     \
                 : "r"(addr))
#define LDSM4T(r, addr)                                                       \
    asm volatile("ldmatrix.sync.aligned.m8n8.x4.trans.shared.b16 {%0,%1,%2,%3}, [%4];" \
                 : "=r"((r)[0]), "=r"((r)[1]), "=r"((r)[2]), "=r"((r)[3])     \
                 : "r"(addr))

// main term: f16 inputs, f32 accumulate
#define MMAF32(d, a, b)                                                       \
    asm volatile(                                                             \
        "mma.sync.aligned.m16n8k16.row.col.f32.f16.f16.f32 "                  \
        "{%0,%1,%2,%3}, {%4,%5,%6,%7}, {%8,%9}, {%0,%1,%2,%3};"               \
        : "+f"((d)[0]), "+f"((d)[1]), "+f"((d)[2]), "+f"((d)[3])              \
        : "r"((a)[0]), "r"((a)[1]), "r"((a)[2]), "r"((a)[3]),                 \
          "r"((b)[0]), "r"((b)[1]))

// correction terms: f16 inputs, f16 accumulate (potentially 2x rate)
#define MMAF16(d, a, b)                                                       \
    asm volatile(                                                             \
        "mma.sync.aligned.m16n8k16.row.col.f16.f16.f16.f16 "                  \
        "{%0,%1}, {%2,%3,%4,%5}, {%6,%7}, {%0,%1};"                           \
        : "+r"((d)[0]), "+r"((d)[1])                                          \
        : "r"((a)[0]), "r"((a)[1]), "r"((a)[2]), "r"((a)[3]),                 \
          "r"((b)[0]), "r"((b)[1]))

__device__ __forceinline__ float2 h2f2(uint32_t u) {
    __half2 h = *(__half2*)&u;
    return __half22float2(h);
}
__device__ __forceinline__ uint32_t f2h2(float x, float y) {
    __half2 h = __float22half2_rn(make_float2(x, y));
    return *(uint32_t*)&h;
}

// ---------------------------------------------------------------------------
// fp32 -> fp16 hi/lo split
// ---------------------------------------------------------------------------
__device__ __forceinline__ void split1(float x, unsigned short& h, unsigned short& l) {
    __half hb = __float2half_rn(x);
    __half lb = __float2half_rn(x - __half2float(hb));
    h = __half_as_ushort(hb);
    l = __half_as_ushort(lb);
}

// Activations: src [M,K] fp32 -> g_xhi/g_xlo fp16.
__global__ void asplit_kernel(const float* __restrict__ src) {
    size_t i = (size_t)blockIdx.x * 256 + threadIdx.x;
    float4 v = ((const float4*)src)[i];
    ushort4 h, l;
    split1(v.x, h.x, l.x);
    split1(v.y, h.y, l.y);
    split1(v.z, h.z, l.z);
    split1(v.w, h.w, l.w);
    ((ushort4*)g_xhi)[i] = h;
    ((ushort4*)g_xlo)[i] = l;
}

// Weights: W [K,N] fp32 -> g_bhi/g_blo slot widx, [N,K] fp16 (transposed)
__global__ void wsplit_kernel(const float* __restrict__ W, int widx) {
    __shared__ float ts[32][33];
    const int tx = threadIdx.x, ty = threadIdx.y;
    const int n0 = blockIdx.x * 32, k0 = blockIdx.y * 32;
    __half* bh = g_bhi + (size_t)widx * HID_ * HID_;
    __half* bl = g_blo + (size_t)widx * HID_ * HID_;
#pragma unroll
    for (int i = 0; i < 4; i++)
        ts[ty + 8 * i][tx] = W[(size_t)(k0 + ty + 8 * i) * HID_ + n0 + tx];
    __syncthreads();
#pragma unroll
    for (int i = 0; i < 4; i++) {
        int n = n0 + ty + 8 * i;
        int k = k0 + tx;
        float v = ts[tx][ty + 8 * i];
        unsigned short h, l;
        split1(v, h, l);
        bh[(size_t)n * HID_ + k] = __ushort_as_half(h);
        bl[(size_t)n * HID_ + k] = __ushort_as_half(l);
    }
}

// ---------------------------------------------------------------------------
// mma.sync fp16x3 GEMM, 3-stage cp.async pipeline.
// Main term f32-accum; corrections f16-accum (merged in epilogue).
// MODE==1: fused QKV (blockIdx.x = widx*16 + head). MODE==0: O projection.
// ---------------------------------------------------------------------------
#define PITCH 144
#define MATB  (128 * PITCH)
#define BUFB  (4 * MATB)
#define GEMM_SMEM (3 * BUFB)         // 221184
#define NCH (HID_ / 64)              // 32

template <int MODE>
__global__ __launch_bounds__(256, 1) void mma_gemm(float* __restrict__ Cout) {
    extern __shared__ char dsm[];
    const uint32_t sb = smem_u32(dsm);
    const int t = threadIdx.x;
    const int lane = t & 31, wid = t >> 5;
    const int wm = wid & 3, wn = wid >> 2;
    const int m0 = blockIdx.y * 128;
    const int widx = (MODE == 1) ? (blockIdx.x >> 4) : 3;
    const int nblk = (MODE == 1) ? (blockIdx.x & 15) : blockIdx.x;
    const int n0 = nblk * 128;

    const __half* __restrict__ AH = g_xhi;
    const __half* __restrict__ AL = g_xlo;
    const __half* __restrict__ BH = g_bhi + (size_t)widx * HID_ * HID_;
    const __half* __restrict__ BL = g_blo + (size_t)widx * HID_ * HID_;

    float accF[2][8][4];
    uint32_t accC[2][8][2];
#pragma unroll
    for (int i = 0; i < 2; i++)
#pragma unroll
        for (int j = 0; j < 8; j++) {
#pragma unroll
            for (int k = 0; k < 4; k++) accF[i][j][k] = 0.f;
            accC[i][j][0] = 0u;
            accC[i][j][1] = 0u;
        }

    const int lrow = t >> 3;
    const int lch = t & 7;

#pragma unroll
    for (int s = 0; s < 2; s++) {
        const uint32_t base = sb + s * BUFB;
        const int k0 = s * 64;
#pragma unroll
        for (int j = 0; j < 4; j++) {
            int row = lrow + j * 32;
            uint32_t sa = base + row * PITCH + lch * 16;
            size_t ga = (size_t)(m0 + row) * HID_ + k0 + lch * 8;
            size_t gb = (size_t)(n0 + row) * HID_ + k0 + lch * 8;
            cpa16(sa, AH + ga);
            cpa16(sa + MATB, AL + ga);
            cpa16(sa + 2 * MATB, BH + gb);
            cpa16(sa + 3 * MATB, BL + gb);
        }
        CP_COMMIT();
    }

    const uint32_t lm_a_off =
        (uint32_t)((wm * 32 + (lane & 15)) * PITCH + (lane >> 4) * 16);
    const uint32_t lm_b_off =
        (uint32_t)((wn * 64 + (lane & 15)) * PITCH + (lane >> 4) * 16);

    int bufn = 0;
    int pbuf = 2;
    for (int c = 0; c < NCH; c++) {
        CP_WAIT1();
        __syncthreads();

        if (c + 2 < NCH) {
            const uint32_t base = sb + pbuf * BUFB;
            const int k0 = (c + 2) * 64;
#pragma unroll
            for (int j = 0; j < 4; j++) {
                int row = lrow + j * 32;
                uint32_t sa = base + row * PITCH + lch * 16;
                size_t ga = (size_t)(m0 + row) * HID_ + k0 + lch * 8;
                size_t gb = (size_t)(n0 + row) * HID_ + k0 + lch * 8;
                cpa16(sa, AH + ga);
                cpa16(sa + MATB, AL + ga);
                cpa16(sa + 2 * MATB, BH + gb);
                cpa16(sa + 3 * MATB, BL + gb);
            }
        }
        CP_COMMIT();

        const uint32_t cb = sb + bufn * BUFB;
#pragma unroll
        for (int ks = 0; ks < 4; ks++) {
            uint32_t ah[2][4], al[2][4];
#pragma unroll
            for (int mt = 0; mt < 2; mt++) {
                uint32_t addr = cb + lm_a_off + mt * (16 * PITCH) + ks * 32;
                LDSM4(ah[mt], addr);
                LDSM4(al[mt], addr + MATB);
            }
            uint32_t bh[8][2], bl[8][2];
#pragma unroll
            for (int np = 0; np < 4; np++) {
                uint32_t addr = cb + 2 * MATB + lm_b_off + np * (16 * PITCH) + ks * 32;
                uint32_t r[4];
                LDSM4(r, addr);
                bh[2 * np][0] = r[0]; bh[2 * np + 1][0] = r[1];
                bh[2 * np][1] = r[2]; bh[2 * np + 1][1] = r[3];
                LDSM4(r, addr + MATB);
                bl[2 * np][0] = r[0]; bl[2 * np + 1][0] = r[1];
                bl[2 * np][1] = r[2]; bl[2 * np + 1][1] = r[3];
            }
#pragma unroll
            for (int mt = 0; mt < 2; mt++)
#pragma unroll
                for (int nt = 0; nt < 8; nt++) {
                    MMAF32(accF[mt][nt], ah[mt], bh[nt]);
                    MMAF16(accC[mt][nt], al[mt], bh[nt]);
                    MMAF16(accC[mt][nt], ah[mt], bl[nt]);
                }
        }
        bufn = (bufn == 2) ? 0 : bufn + 1;
        pbuf = (pbuf == 2) ? 0 : pbuf + 1;
    }

    // Epilogue: merge f16 corrections into f32, then write
    const int qrow = lane >> 2;
    const int qcol = (lane & 3) * 2;
#pragma unroll
    for (int mt = 0; mt < 2; mt++) {
#pragma unroll
        for (int nt = 0; nt < 8; nt++) {
            float2 c0 = h2f2(accC[mt][nt][0]);
            float2 c1 = h2f2(accC[mt][nt][1]);
            accF[mt][nt][0] += c0.x;
            accF[mt][nt][1] += c0.y;
            accF[mt][nt][2] += c1.x;
            accF[mt][nt][3] += c1.y;
        }
#pragma unroll
        for (int half_ = 0; half_ < 2; half_++) {
            const int m = m0 + wm * 32 + mt * 16 + qrow + half_ * 8;
            if (MODE == 1 && widx == 2) {
                int b_ = m >> 11, s_ = m & (S_ - 1);
                size_t base = (((size_t)b_ * H_ + nblk) * S_ + s_) * D_;
#pragma unroll
                for (int nt = 0; nt < 8; nt++) {
                    int col = wn * 64 + nt * 8 + qcol;
                    float x = accF[mt][nt][half_ * 2];
                    float y = accF[mt][nt][half_ * 2 + 1];
                    unsigned short hx, lx, hy, ly;
                    split1(x, hx, lx);
                    split1(y, hy, ly);
                    *(uint32_t*)(g_vh + base + col) = (uint32_t)hx | ((uint32_t)hy << 16);
                    *(uint32_t*)(g_vl + base + col) = (uint32_t)lx | ((uint32_t)ly << 16);
                }
            } else {
                float* dst;
                size_t base;
                if (MODE == 0) {
                    dst = Cout;
                    base = (size_t)m * HID_ + n0;
                } else {
                    int b_ = m >> 11, s_ = m & (S_ - 1);
                    dst = (widx == 0) ? g_q : g_k;
                    base = (((size_t)b_ * H_ + nblk) * S_ + s_) * D_;
                }
#pragma unroll
                for (int nt = 0; nt < 8; nt++) {
                    int col = wn * 64 + nt * 8 + qcol;
                    *(float2*)(dst + base + col) =
                        make_float2(accF[mt][nt][half_ * 2], accF[mt][nt][half_ * 2 + 1]);
                }
            }
        }
    }
}

// ---------------------------------------------------------------------------
// RoPE: read fp32 g_q/g_k, rotate, split to fp16 hi/lo.
// ---------------------------------------------------------------------------
__global__ void rope_split_kernel(const float* __restrict__ cosb,
                                  const float* __restrict__ sinb) {
    int tid = blockIdx.x * 256 + threadIdx.x;
    int d = tid & 63;
    int s = (tid >> 6) & (S_ - 1);
    int bh = tid >> 17;
    size_t base = ((size_t)bh * S_ + s) * D_;
    float c0 = cosb[s * D_ + d], c1 = cosb[s * D_ + d + 64];
    float s0 = sinb[s * D_ + d], s1 = sinb[s * D_ + d + 64];

    float q0 = g_q[base + d], q1 = g_q[base + d + 64];
    float k0 = g_k[base + d], k1 = g_k[base + d + 64];
    float qa = q0 * c0 - q1 * s0;
    float qb = q1 * c1 + q0 * s1;
    float ka = k0 * c0 - k1 * s0;
    float kb = k1 * c1 + k0 * s1;

    unsigned short h, l;
    split1(qa, h, l);
    g_qh[base + d] = __ushort_as_half(h);
    g_ql[base + d] = __ushort_as_half(l);
    split1(qb, h, l);
    g_qh[base + d + 64] = __ushort_as_half(h);
    g_ql[base + d + 64] = __ushort_as_half(l);
    split1(ka, h, l);
    g_kh[base + d] = __ushort_as_half(h);
    g_kl[base + d] = __ushort_as_half(l);
    split1(kb, h, l);
    g_kh[base + d + 64] = __ushort_as_half(h);
    g_kl[base + d + 64] = __ushort_as_half(l);
}

// ---------------------------------------------------------------------------
// Flash attention, fp16x3 mma. Corrections in f16-accum, merged per k-tile.
// Epilogue writes xhi/xlo fp16 splits directly (feeds O-projection).
// ---------------------------------------------------------------------------
#define AP   272
#define AMAT (128 * AP)
#define ATTN_SMEM (6 * AMAT)          // 208896

__global__ __launch_bounds__(256, 1) void attn_mma_kernel() {
    extern __shared__ char sm8[];
    const uint32_t sb = smem_u32(sm8);
    const uint32_t Qh = sb,            Ql = sb + AMAT;
    const uint32_t Kh = sb + 2 * AMAT, Kl = sb + 3 * AMAT;
    const uint32_t Vh = sb + 4 * AMAT, Vl = sb + 5 * AMAT;

    const int t = threadIdx.x, lane = t & 31, wid = t >> 5;
    const int bh = blockIdx.y;
    const int q0 = blockIdx.x * 128;
    const size_t qoff = ((size_t)bh * S_ + q0) * D_;
    const size_t koff = (size_t)bh * S_ * D_;

#pragma unroll
    for (int j = 0; j < 8; j++) {
        int idx = t + j * 256;
        int row = idx >> 4, ch = idx & 15;
        uint32_t so = (uint32_t)(row * AP + ch * 16);
        size_t go = qoff + (size_t)row * D_ + ch * 8;
        cpa16(Qh + so, g_qh + go);
        cpa16(Ql + so, g_ql + go);
    }
    CP_COMMIT();

    float sa[16][4];
    float oa[16][4];
    uint32_t csa[16][2], coa[16][2];
#pragma unroll
    for (int i = 0; i < 16; i++)
#pragma unroll
        for (int j = 0; j < 4; j++) oa[i][j] = 0.f;
    float m0r = -1e30f, m1r = -1e30f, l0r = 0.f, l1r = 0.f;

    const float scale = 0.088388347648318447f;
    const uint32_t a_off =
        (uint32_t)((wid * 16 + (lane & 15)) * AP + (lane >> 4) * 16);
    const uint32_t lm_lo = (uint32_t)((lane & 15) * AP + (lane >> 4) * 16);

    for (int kt = 0; kt < S_ / 128; kt++) {
        __syncthreads();
#pragma unroll
        for (int j = 0; j < 8; j++) {
            int idx = t + j * 256;
            int row = idx >> 4, ch = idx & 15;
            uint32_t so = (uint32_t)(row * AP + ch * 16);
            size_t go = koff + (size_t)(kt * 128 + row) * D_ + ch * 8;
            cpa16(Kh + so, g_kh + go);
            cpa16(Kl + so, g_kl + go);
        }
        CP_COMMIT();
#pragma unroll
        for (int j = 0; j < 8; j++) {
            int idx = t + j * 256;
            int row = idx >> 4, ch = idx & 15;
            uint32_t so = (uint32_t)(row * AP + ch * 16);
            size_t go = koff + (size_t)(kt * 128 + row) * D_ + ch * 8;
            cpa16(Vh + so, g_vh + go);
            cpa16(Vl + so, g_vl + go);
        }
        CP_COMMIT();

        CP_WAIT1();
        __syncthreads();

#pragma unroll
        for (int i = 0; i < 16; i++) {
#pragma unroll
            for (int j = 0; j < 4; j++) sa[i][j] = 0.f;
            csa[i][0] = 0u;
            csa[i][1] = 0u;
        }

#pragma unroll
        for (int ks = 0; ks < 8; ks++) {
            uint32_t qh[4], ql[4];
            LDSM4(qh, Qh + a_off + ks * 32);
            LDSM4(ql, Ql + a_off + ks * 32);
#pragma unroll
            for (int np = 0; np < 8; np++) {
                uint32_t boff = lm_lo + (uint32_t)(np * 16 * AP) + ks * 32;
                uint32_t r[4], kh0[2], kh1[2], kl0[2], kl1[2];
                LDSM4(r, Kh + boff);
                kh0[0] = r[0]; kh1[0] = r[1]; kh0[1] = r[2]; kh1[1] = r[3];
                LDSM4(r, Kl + boff);
                kl0[0] = r[0]; kl1[0] = r[1]; kl0[1] = r[2]; kl1[1] = r[3];
                MMAF32(sa[2 * np], qh, kh0);
                MMAF16(csa[2 * np], ql, kh0);
                MMAF16(csa[2 * np], qh, kl0);
                MMAF32(sa[2 * np + 1], qh, kh1);
                MMAF16(csa[2 * np + 1], ql, kh1);
                MMAF16(csa[2 * np + 1], qh, kl1);
            }
        }
        // merge S corrections
#pragma unroll
        for (int i = 0; i < 16; i++) {
            float2 c0 = h2f2(csa[i][0]);
            float2 c1 = h2f2(csa[i][1]);
            sa[i][0] += c0.x; sa[i][1] += c0.y;
            sa[i][2] += c1.x; sa[i][3] += c1.y;
        }

        // ---- online softmax ----
        float rm0 = -1e30f, rm1 = -1e30f;
#pragma unroll
        for (int nt = 0; nt < 16; nt++) {
            rm0 = fmaxf(rm0, fmaxf(sa[nt][0], sa[nt][1]));
            rm1 = fmaxf(rm1, fmaxf(sa[nt][2], sa[nt][3]));
        }
#pragma unroll
        for (int off = 1; off <= 2; off <<= 1) {
            rm0 = fmaxf(rm0, __shfl_xor_sync(0xffffffffu, rm0, off));
            rm1 = fmaxf(rm1, __shfl_xor_sync(0xffffffffu, rm1, off));
        }
        float mn0 = fmaxf(m0r, rm0 * scale);
        float mn1 = fmaxf(m1r, rm1 * scale);
        float al0 = __expf(m0r - mn0);
        float al1 = __expf(m1r - mn1);
        m0r = mn0;
        m1r = mn1;
        float rs0 = 0.f, rs1 = 0.f;
#pragma unroll
        for (int nt = 0; nt < 16; nt++) {
            float p0 = __expf(fmaf(sa[nt][0], scale, -mn0));
            float p1 = __expf(fmaf(sa[nt][1], scale, -mn0));
            float p2 = __expf(fmaf(sa[nt][2], scale, -mn1));
            float p3 = __expf(fmaf(sa[nt][3], scale, -mn1));
            sa[nt][0] = p0; sa[nt][1] = p1; sa[nt][2] = p2; sa[nt][3] = p3;
            rs0 += p0 + p1;
            rs1 += p2 + p3;
        }
#pragma unroll
        for (int off = 1; off <= 2; off <<= 1) {
            rs0 += __shfl_xor_sync(0xffffffffu, rs0, off);
            rs1 += __shfl_xor_sync(0xffffffffu, rs1, off);
        }
        l0r = l0r * al0 + rs0;
        l1r = l1r * al1 + rs1;
#pragma unroll
        for (int nt = 0; nt < 16; nt++) {
            oa[nt][0] *= al0;
            oa[nt][1] *= al0;
            oa[nt][2] *= al1;
            oa[nt][3] *= al1;
            coa[nt][0] = 0u;
            coa[nt][1] = 0u;
        }

        CP_WAIT0();
        __syncthreads();

        // ---- O += P V (main f32, corrections f16-accum) ----
#pragma unroll
        for (int ks = 0; ks < 8; ks++) {
            uint32_t aH[4], aL[4];
#pragma unroll
            for (int g = 0; g < 2; g++) {
                const int tt = 2 * ks + g;
                float x0 = sa[tt][0], y0 = sa[tt][1];
                float x1 = sa[tt][2], y1 = sa[tt][3];
                uint32_t h0 = f2h2(x0, y0);
                uint32_t h1 = f2h2(x1, y1);
                float2 b0 = h2f2(h0);
                float2 b1 = h2f2(h1);
                aH[2 * g]     = h0;
                aH[2 * g + 1] = h1;
                aL[2 * g]     = f2h2(x0 - b0.x, y0 - b0.y);
                aL[2 * g + 1] = f2h2(x1 - b1.x, y1 - b1.y);
            }
            const uint32_t vbase = lm_lo + (uint32_t)(ks * 16 * AP);
#pragma unroll
            for (int np = 0; np < 8; np++) {
                uint32_t r[4], vh0[2], vh1[2], vl0[2], vl1[2];
                LDSM4T(r, Vh + vbase + np * 32);
                vh0[0] = r[0]; vh0[1] = r[1]; vh1[0] = r[2]; vh1[1] = r[3];
                LDSM4T(r, Vl + vbase + np * 32);
                vl0[0] = r[0]; vl0[1] = r[1]; vl1[0] = r[2]; vl1[1] = r[3];
                MMAF32(oa[2 * np], aH, vh0);
                MMAF16(coa[2 * np], aL, vh0);
                MMAF16(coa[2 * np], aH, vl0);
                MMAF32(oa[2 * np + 1], aH, vh1);
                MMAF16(coa[2 * np + 1], aL, vh1);
                MMAF16(coa[2 * np + 1], aH, vl1);
            }
        }
        // merge O corrections (before next iteration's alpha rescale)
#pragma unroll
        for (int i = 0; i < 16; i++) {
            float2 c0 = h2f2(coa[i][0]);
            float2 c1 = h2f2(coa[i][1]);
            oa[i][0] += c0.x; oa[i][1] += c0.y;
            oa[i][2] += c1.x; oa[i][3] += c1.y;
        }
    }

    // ---- finalize: write xhi/xlo fp16 splits of attn output directly ----
    const int b_ = bh >> 4, h = bh & 15;
    const int row0 = q0 + wid * 16 + (lane >> 2);
    const float inv0 = 1.0f / l0r, inv1 = 1.0f / l1r;
    const size_t base0 = ((size_t)b_ * S_ + row0) * HID_ + h * D_;
    const size_t base1 = ((size_t)b_ * S_ + row0 + 8) * HID_ + h * D_;
    const int col0 = (lane & 3) * 2;
#pragma unroll
    for (int nt = 0; nt < 16; nt++) {
        int col = 8 * nt + col0;
        float x0 = oa[nt][0] * inv0, y0 = oa[nt][1] * inv0;
        float x1 = oa[nt][2] * inv1, y1 = oa[nt][3] * inv1;
        unsigned short hx, lx, hy, ly;
        split1(x0, hx, lx);
        split1(y0, hy, ly);
        *(uint32_t*)(g_xhi + base0 + col) = (uint32_t)hx | ((uint32_t)hy << 16);
        *(uint32_t*)(g_xlo + base0 + col) = (uint32_t)lx | ((uint32_t)ly << 16);
        split1(x1, hx, lx);
        split1(y1, hy, ly);
        *(uint32_t*)(g_xhi + base1 + col) = (uint32_t)hx | ((uint32_t)hy << 16);
        *(uint32_t*)(g_xlo + base1 + col) = (uint32_t)lx | ((uint32_t)ly << 16);
    }
}

// ---------------------------------------------------------------------------
// Launch
// ---------------------------------------------------------------------------
extern "C" void kernel_launch(void* const* d_in, const int* in_sizes, int n_in,
                              void* d_out, int out_size) {
    const float* X = (const float*)d_in[0];
    const float* cosb = (const float*)d_in[1];
    const float* sinb = (const float*)d_in[2];
    const float* Wq = (const float*)d_in[3];
    const float* Wk = (const float*)d_in[4];
    const float* Wv = (const float*)d_in[5];
    const float* Wo = (const float*)d_in[6];
    float* out = (float*)d_out;

    cudaFuncSetAttribute(mma_gemm<0>, cudaFuncAttributeMaxDynamicSharedMemorySize, GEMM_SMEM);
    cudaFuncSetAttribute(mma_gemm<1>, cudaFuncAttributeMaxDynamicSharedMemorySize, GEMM_SMEM);
    cudaFuncSetAttribute(attn_mma_kernel, cudaFuncAttributeMaxDynamicSharedMemorySize, ATTN_SMEM);

    const dim3 wgrid(64, 64);
    const dim3 wblk(32, 8);

    wsplit_kernel<<<wgrid, wblk>>>(Wq, 0);
    wsplit_kernel<<<wgrid, wblk>>>(Wk, 1);
    wsplit_kernel<<<wgrid, wblk>>>(Wv, 2);
    wsplit_kernel<<<wgrid, wblk>>>(Wo, 3);
    asplit_kernel<<<(M_ * HID_ / 4) / 256, 256>>>(X);

    // fused QKV projection
    mma_gemm<1><<<dim3(48, M_ / 128), 256, GEMM_SMEM>>>(nullptr);

    rope_split_kernel<<<(B_ * H_ * S_ * 64) / 256, 256>>>(cosb, sinb);

    // attention writes g_xhi/g_xlo directly
    attn_mma_kernel<<<dim3(S_ / 128, B_ * H_), 256, ATTN_SMEM>>>();

    // O projection
    mma_gemm<0><<<dim3(HID_ / 128, M_ / 128), 256, GEMM_SMEM>>>(out);
}

// round 7
// speedup vs baseline: 3.3045x; 1.4010x over previous
#include <cuda_runtime.h>
#include <cuda_fp16.h>
#include <cstdint>

// ---------------------------------------------------------------------------
// Problem constants
// ---------------------------------------------------------------------------
#define B_ 2
#define S_ 2048
#define H_ 16
#define D_ 128
#define HID_ 2048
#define M_ (B_ * S_)   // 4096

// Scratch (device globals — allocation-free per harness rules)
__device__ float g_q[(size_t)B_ * H_ * S_ * D_];   // fp32 Q pre-rope [b,h,s,d]
__device__ float g_k[(size_t)B_ * H_ * S_ * D_];   // fp32 K pre-rope

// fp16 buffers. Activations split hi/lo; weights hi only (2-term emulation).
__device__ __half g_xhi[(size_t)M_ * HID_];
__device__ __half g_xlo[(size_t)M_ * HID_];
__device__ __half g_bhi[(size_t)4 * HID_ * HID_];

// fp16 attention operands [b,h,s,d]: Q split hi/lo; K, V hi only.
#define QKV_ELEMS ((size_t)B_ * H_ * S_ * D_)
__device__ __half g_qh[QKV_ELEMS];
__device__ __half g_ql[QKV_ELEMS];
__device__ __half g_kh[QKV_ELEMS];
__device__ __half g_vh[QKV_ELEMS];

// ---------------------------------------------------------------------------
// PTX helpers (non-'a' features only)
// ---------------------------------------------------------------------------
__device__ __forceinline__ uint32_t smem_u32(const void* p) {
    uint32_t a;
    asm("{ .reg .u64 t; cvta.to.shared.u64 t, %1; cvt.u32.u64 %0, t; }"
        : "=r"(a) : "l"(p));
    return a;
}
__device__ __forceinline__ void cpa16(uint32_t s, const void* g) {
    asm volatile("cp.async.cg.shared.global [%0], [%1], 16;" :: "r"(s), "l"(g));
}
#define CP_COMMIT() asm volatile("cp.async.commit_group;" ::: "memory")
#define CP_WAIT0()  asm volatile("cp.async.wait_group 0;" ::: "memory")
#define CP_WAIT1()  asm volatile("cp.async.wait_group 1;" ::: "memory")

#define LDSM4(r, addr)                                                        \
    asm volatile("ldmatrix.sync.aligned.m8n8.x4.shared.b16 {%0,%1,%2,%3}, [%4];" \
                 : "=r"((r)[0]), "=r"((r)[1]), "=r"((r)[2]), "=r"((r)[3])     \
                 : "r"(addr))
#define LDSM4T(r, addr)                                                       \
    asm volatile("ldmatrix.sync.aligned.m8n8.x4.trans.shared.b16 {%0,%1,%2,%3}, [%4];" \
                 : "=r"((r)[0]), "=r"((r)[1]), "=r"((r)[2]), "=r"((r)[3])     \
                 : "r"(addr))

#define MMAF32(d, a, b)                                                       \
    asm volatile(                                                             \
        "mma.sync.aligned.m16n8k16.row.col.f32.f16.f16.f32 "                  \
        "{%0,%1,%2,%3}, {%4,%5,%6,%7}, {%8,%9}, {%0,%1,%2,%3};"               \
        : "+f"((d)[0]), "+f"((d)[1]), "+f"((d)[2]), "+f"((d)[3])              \
        : "r"((a)[0]), "r"((a)[1]), "r"((a)[2]), "r"((a)[3]),                 \
          "r"((b)[0]), "r"((b)[1]))

__device__ __forceinline__ float2 h2f2(uint32_t u) {
    __half2 h = *(__half2*)&u;
    return __half22float2(h);
}
__device__ __forceinline__ uint32_t f2h2(float x, float y) {
    __half2 h = __float22half2_rn(make_float2(x, y));
    return *(uint32_t*)&h;
}

// ---------------------------------------------------------------------------
// fp32 -> fp16 hi/lo split
// ---------------------------------------------------------------------------
__device__ __forceinline__ void split1(float x, unsigned short& h, unsigned short& l) {
    __half hb = __float2half_rn(x);
    __half lb = __float2half_rn(x - __half2float(hb));
    h = __half_as_ushort(hb);
    l = __half_as_ushort(lb);
}

// Activations: src [M,K] fp32 -> g_xhi/g_xlo fp16.
__global__ void asplit_kernel(const float* __restrict__ src) {
    size_t i = (size_t)blockIdx.x * 256 + threadIdx.x;
    float4 v = ((const float4*)src)[i];
    ushort4 h, l;
    split1(v.x, h.x, l.x);
    split1(v.y, h.y, l.y);
    split1(v.z, h.z, l.z);
    split1(v.w, h.w, l.w);
    ((ushort4*)g_xhi)[i] = h;
    ((ushort4*)g_xlo)[i] = l;
}

// Weights: W [K,N] fp32 -> g_bhi slot widx, [N,K] fp16 (transposed, hi only)
__global__ void wsplit_kernel(const float* __restrict__ W, int widx) {
    __shared__ float ts[32][33];
    const int tx = threadIdx.x, ty = threadIdx.y;
    const int n0 = blockIdx.x * 32, k0 = blockIdx.y * 32;
    __half* bh = g_bhi + (size_t)widx * HID_ * HID_;
#pragma unroll
    for (int i = 0; i < 4; i++)
        ts[ty + 8 * i][tx] = W[(size_t)(k0 + ty + 8 * i) * HID_ + n0 + tx];
    __syncthreads();
#pragma unroll
    for (int i = 0; i < 4; i++) {
        int n = n0 + ty + 8 * i;
        int k = k0 + tx;
        bh[(size_t)n * HID_ + k] = __float2half_rn(ts[tx][ty + 8 * i]);
    }
}

// ---------------------------------------------------------------------------
// mma.sync fp16x2 GEMM (Ah*Bh + Al*Bh, both f32-accum), 3-stage pipeline.
// MODE==1: fused QKV (blockIdx.x = widx*16 + head). MODE==0: O projection.
// ---------------------------------------------------------------------------
#define PITCH 144
#define MATB  (128 * PITCH)          // 18432
#define BUFB  (3 * MATB)             // 55296 (Ah, Al, Bh)
#define GEMM_SMEM (3 * BUFB)         // 165888
#define NCH (HID_ / 64)              // 32

template <int MODE>
__global__ __launch_bounds__(256, 1) void mma_gemm(float* __restrict__ Cout) {
    extern __shared__ char dsm[];
    const uint32_t sb = smem_u32(dsm);
    const int t = threadIdx.x;
    const int lane = t & 31, wid = t >> 5;
    const int wm = wid & 3, wn = wid >> 2;
    const int m0 = blockIdx.y * 128;
    const int widx = (MODE == 1) ? (blockIdx.x >> 4) : 3;
    const int nblk = (MODE == 1) ? (blockIdx.x & 15) : blockIdx.x;
    const int n0 = nblk * 128;

    const __half* __restrict__ AH = g_xhi;
    const __half* __restrict__ AL = g_xlo;
    const __half* __restrict__ BH = g_bhi + (size_t)widx * HID_ * HID_;

    float acc[2][8][4];
#pragma unroll
    for (int i = 0; i < 2; i++)
#pragma unroll
        for (int j = 0; j < 8; j++)
#pragma unroll
            for (int k = 0; k < 4; k++) acc[i][j][k] = 0.f;

    const int lrow = t >> 3;
    const int lch = t & 7;

#pragma unroll
    for (int s = 0; s < 2; s++) {
        const uint32_t base = sb + s * BUFB;
        const int k0 = s * 64;
#pragma unroll
        for (int j = 0; j < 4; j++) {
            int row = lrow + j * 32;
            uint32_t sa = base + row * PITCH + lch * 16;
            size_t ga = (size_t)(m0 + row) * HID_ + k0 + lch * 8;
            size_t gb = (size_t)(n0 + row) * HID_ + k0 + lch * 8;
            cpa16(sa, AH + ga);
            cpa16(sa + MATB, AL + ga);
            cpa16(sa + 2 * MATB, BH + gb);
        }
        CP_COMMIT();
    }

    const uint32_t lm_a_off =
        (uint32_t)((wm * 32 + (lane & 15)) * PITCH + (lane >> 4) * 16);
    const uint32_t lm_b_off =
        (uint32_t)((wn * 64 + (lane & 15)) * PITCH + (lane >> 4) * 16);

    int bufn = 0;
    int pbuf = 2;
    for (int c = 0; c < NCH; c++) {
        CP_WAIT1();
        __syncthreads();

        if (c + 2 < NCH) {
            const uint32_t base = sb + pbuf * BUFB;
            const int k0 = (c + 2) * 64;
#pragma unroll
            for (int j = 0; j < 4; j++) {
                int row = lrow + j * 32;
                uint32_t sa = base + row * PITCH + lch * 16;
                size_t ga = (size_t)(m0 + row) * HID_ + k0 + lch * 8;
                size_t gb = (size_t)(n0 + row) * HID_ + k0 + lch * 8;
                cpa16(sa, AH + ga);
                cpa16(sa + MATB, AL + ga);
                cpa16(sa + 2 * MATB, BH + gb);
            }
        }
        CP_COMMIT();

        const uint32_t cb = sb + bufn * BUFB;
#pragma unroll
        for (int ks = 0; ks < 4; ks++) {
            uint32_t ah[2][4], al[2][4];
#pragma unroll
            for (int mt = 0; mt < 2; mt++) {
                uint32_t addr = cb + lm_a_off + mt * (16 * PITCH) + ks * 32;
                LDSM4(ah[mt], addr);
                LDSM4(al[mt], addr + MATB);
            }
            uint32_t bh[8][2];
#pragma unroll
            for (int np = 0; np < 4; np++) {
                uint32_t addr = cb + 2 * MATB + lm_b_off + np * (16 * PITCH) + ks * 32;
                uint32_t r[4];
                LDSM4(r, addr);
                bh[2 * np][0] = r[0]; bh[2 * np + 1][0] = r[1];
                bh[2 * np][1] = r[2]; bh[2 * np + 1][1] = r[3];
            }
#pragma unroll
            for (int mt = 0; mt < 2; mt++)
#pragma unroll
                for (int nt = 0; nt < 8; nt++) {
                    MMAF32(acc[mt][nt], ah[mt], bh[nt]);
                    MMAF32(acc[mt][nt], al[mt], bh[nt]);
                }
        }
        bufn = (bufn == 2) ? 0 : bufn + 1;
        pbuf = (pbuf == 2) ? 0 : pbuf + 1;
    }

    // Epilogue
    const int qrow = lane >> 2;
    const int qcol = (lane & 3) * 2;
#pragma unroll
    for (int mt = 0; mt < 2; mt++) {
#pragma unroll
        for (int half_ = 0; half_ < 2; half_++) {
            const int m = m0 + wm * 32 + mt * 16 + qrow + half_ * 8;
            if (MODE == 1 && widx == 2) {
                // V: round to fp16 hi directly
                int b_ = m >> 11, s_ = m & (S_ - 1);
                size_t base = (((size_t)b_ * H_ + nblk) * S_ + s_) * D_;
#pragma unroll
                for (int nt = 0; nt < 8; nt++) {
                    int col = wn * 64 + nt * 8 + qcol;
                    *(uint32_t*)(g_vh + base + col) =
                        f2h2(acc[mt][nt][half_ * 2], acc[mt][nt][half_ * 2 + 1]);
                }
            } else {
                float* dst;
                size_t base;
                if (MODE == 0) {
                    dst = Cout;
                    base = (size_t)m * HID_ + n0;
                } else {
                    int b_ = m >> 11, s_ = m & (S_ - 1);
                    dst = (widx == 0) ? g_q : g_k;
                    base = (((size_t)b_ * H_ + nblk) * S_ + s_) * D_;
                }
#pragma unroll
                for (int nt = 0; nt < 8; nt++) {
                    int col = wn * 64 + nt * 8 + qcol;
                    *(float2*)(dst + base + col) =
                        make_float2(acc[mt][nt][half_ * 2], acc[mt][nt][half_ * 2 + 1]);
                }
            }
        }
    }
}

// ---------------------------------------------------------------------------
// RoPE: read fp32 g_q/g_k, rotate, emit qh/ql (split) and kh (round).
// ---------------------------------------------------------------------------
__global__ void rope_split_kernel(const float* __restrict__ cosb,
                                  const float* __restrict__ sinb) {
    int tid = blockIdx.x * 256 + threadIdx.x;
    int d = tid & 63;
    int s = (tid >> 6) & (S_ - 1);
    int bh = tid >> 17;
    size_t base = ((size_t)bh * S_ + s) * D_;
    float c0 = cosb[s * D_ + d], c1 = cosb[s * D_ + d + 64];
    float s0 = sinb[s * D_ + d], s1 = sinb[s * D_ + d + 64];

    float q0 = g_q[base + d], q1 = g_q[base + d + 64];
    float k0 = g_k[base + d], k1 = g_k[base + d + 64];
    float qa = q0 * c0 - q1 * s0;
    float qb = q1 * c1 + q0 * s1;
    float ka = k0 * c0 - k1 * s0;
    float kb = k1 * c1 + k0 * s1;

    unsigned short h, l;
    split1(qa, h, l);
    g_qh[base + d] = __ushort_as_half(h);
    g_ql[base + d] = __ushort_as_half(l);
    split1(qb, h, l);
    g_qh[base + d + 64] = __ushort_as_half(h);
    g_ql[base + d + 64] = __ushort_as_half(l);
    g_kh[base + d] = __float2half_rn(ka);
    g_kh[base + d + 64] = __float2half_rn(kb);
}

// ---------------------------------------------------------------------------
// Flash attention, fp16x2 mma (Qh*Kh + Ql*Kh; Ph*Vh + Pl*Vh).
// SMEM: Qh, Ql, Kh, Vh each [128][128] fp16 at 272B pitch = 136KB.
// Epilogue writes g_xhi/g_xlo splits directly (feeds O-projection).
// ---------------------------------------------------------------------------
#define AP   272
#define AMAT (128 * AP)
#define ATTN_SMEM (4 * AMAT)          // 139264

__global__ __launch_bounds__(256, 1) void attn_mma_kernel() {
    extern __shared__ char sm8[];
    const uint32_t sb = smem_u32(sm8);
    const uint32_t Qh = sb,            Ql = sb + AMAT;
    const uint32_t Kh = sb + 2 * AMAT, Vh = sb + 3 * AMAT;

    const int t = threadIdx.x, lane = t & 31, wid = t >> 5;
    const int bh = blockIdx.y;
    const int q0 = blockIdx.x * 128;
    const size_t qoff = ((size_t)bh * S_ + q0) * D_;
    const size_t koff = (size_t)bh * S_ * D_;

#pragma unroll
    for (int j = 0; j < 8; j++) {
        int idx = t + j * 256;
        int row = idx >> 4, ch = idx & 15;
        uint32_t so = (uint32_t)(row * AP + ch * 16);
        size_t go = qoff + (size_t)row * D_ + ch * 8;
        cpa16(Qh + so, g_qh + go);
        cpa16(Ql + so, g_ql + go);
    }
    CP_COMMIT();

    float sa[16][4];
    float oa[16][4];
#pragma unroll
    for (int i = 0; i < 16; i++)
#pragma unroll
        for (int j = 0; j < 4; j++) oa[i][j] = 0.f;
    float m0r = -1e30f, m1r = -1e30f, l0r = 0.f, l1r = 0.f;

    const float scale = 0.088388347648318447f;
    const uint32_t a_off =
        (uint32_t)((wid * 16 + (lane & 15)) * AP + (lane >> 4) * 16);
    const uint32_t lm_lo = (uint32_t)((lane & 15) * AP + (lane >> 4) * 16);

    for (int kt = 0; kt < S_ / 128; kt++) {
        __syncthreads();
#pragma unroll
        for (int j = 0; j < 8; j++) {
            int idx = t + j * 256;
            int row = idx >> 4, ch = idx & 15;
            uint32_t so = (uint32_t)(row * AP + ch * 16);
            size_t go = koff + (size_t)(kt * 128 + row) * D_ + ch * 8;
            cpa16(Kh + so, g_kh + go);
        }
        CP_COMMIT();
#pragma unroll
        for (int j = 0; j < 8; j++) {
            int idx = t + j * 256;
            int row = idx >> 4, ch = idx & 15;
            uint32_t so = (uint32_t)(row * AP + ch * 16);
            size_t go = koff + (size_t)(kt * 128 + row) * D_ + ch * 8;
            cpa16(Vh + so, g_vh + go);
        }
        CP_COMMIT();

        CP_WAIT1();
        __syncthreads();

#pragma unroll
        for (int i = 0; i < 16; i++)
#pragma unroll
            for (int j = 0; j < 4; j++) sa[i][j] = 0.f;

#pragma unroll
        for (int ks = 0; ks < 8; ks++) {
            uint32_t qh[4], ql[4];
            LDSM4(qh, Qh + a_off + ks * 32);
            LDSM4(ql, Ql + a_off + ks * 32);
#pragma unroll
            for (int np = 0; np < 8; np++) {
                uint32_t boff = lm_lo + (uint32_t)(np * 16 * AP) + ks * 32;
                uint32_t r[4], kh0[2], kh1[2];
                LDSM4(r, Kh + boff);
                kh0[0] = r[0]; kh1[0] = r[1]; kh0[1] = r[2]; kh1[1] = r[3];
                MMAF32(sa[2 * np], qh, kh0);
                MMAF32(sa[2 * np], ql, kh0);
                MMAF32(sa[2 * np + 1], qh, kh1);
                MMAF32(sa[2 * np + 1], ql, kh1);
            }
        }

        // ---- online softmax ----
        float rm0 = -1e30f, rm1 = -1e30f;
#pragma unroll
        for (int nt = 0; nt < 16; nt++) {
            rm0 = fmaxf(rm0, fmaxf(sa[nt][0], sa[nt][1]));
            rm1 = fmaxf(rm1, fmaxf(sa[nt][2], sa[nt][3]));
        }
#pragma unroll
        for (int off = 1; off <= 2; off <<= 1) {
            rm0 = fmaxf(rm0, __shfl_xor_sync(0xffffffffu, rm0, off));
            rm1 = fmaxf(rm1, __shfl_xor_sync(0xffffffffu, rm1, off));
        }
        float mn0 = fmaxf(m0r, rm0 * scale);
        float mn1 = fmaxf(m1r, rm1 * scale);
        float al0 = __expf(m0r - mn0);
        float al1 = __expf(m1r - mn1);
        m0r = mn0;
        m1r = mn1;
        float rs0 = 0.f, rs1 = 0.f;
#pragma unroll
        for (int nt = 0; nt < 16; nt++) {
            float p0 = __expf(fmaf(sa[nt][0], scale, -mn0));
            float p1 = __expf(fmaf(sa[nt][1], scale, -mn0));
            float p2 = __expf(fmaf(sa[nt][2], scale, -mn1));
            float p3 = __expf(fmaf(sa[nt][3], scale, -mn1));
            sa[nt][0] = p0; sa[nt][1] = p1; sa[nt][2] = p2; sa[nt][3] = p3;
            rs0 += p0 + p1;
            rs1 += p2 + p3;
        }
#pragma unroll
        for (int off = 1; off <= 2; off <<= 1) {
            rs0 += __shfl_xor_sync(0xffffffffu, rs0, off);
            rs1 += __shfl_xor_sync(0xffffffffu, rs1, off);
        }
        l0r = l0r * al0 + rs0;
        l1r = l1r * al1 + rs1;
#pragma unroll
        for (int nt = 0; nt < 16; nt++) {
            oa[nt][0] *= al0;
            oa[nt][1] *= al0;
            oa[nt][2] *= al1;
            oa[nt][3] *= al1;
        }

        CP_WAIT0();
        __syncthreads();

        // ---- O += P V (Ph + Pl, both f32-accum) ----
#pragma unroll
        for (int ks = 0; ks < 8; ks++) {
            uint32_t aH[4], aL[4];
#pragma unroll
            for (int g = 0; g < 2; g++) {
                const int tt = 2 * ks + g;
                float x0 = sa[tt][0], y0 = sa[tt][1];
                float x1 = sa[tt][2], y1 = sa[tt][3];
                uint32_t h0 = f2h2(x0, y0);
                uint32_t h1 = f2h2(x1, y1);
                float2 b0 = h2f2(h0);
                float2 b1 = h2f2(h1);
                aH[2 * g]     = h0;
                aH[2 * g + 1] = h1;
                aL[2 * g]     = f2h2(x0 - b0.x, y0 - b0.y);
                aL[2 * g + 1] = f2h2(x1 - b1.x, y1 - b1.y);
            }
            const uint32_t vbase = lm_lo + (uint32_t)(ks * 16 * AP);
#pragma unroll
            for (int np = 0; np < 8; np++) {
                uint32_t r[4], vh0[2], vh1[2];
                LDSM4T(r, Vh + vbase + np * 32);
                vh0[0] = r[0]; vh0[1] = r[1]; vh1[0] = r[2]; vh1[1] = r[3];
                MMAF32(oa[2 * np], aH, vh0);
                MMAF32(oa[2 * np], aL, vh0);
                MMAF32(oa[2 * np + 1], aH, vh1);
                MMAF32(oa[2 * np + 1], aL, vh1);
            }
        }
    }

    // ---- finalize: write xhi/xlo fp16 splits of attn output directly ----
    const int b_ = bh >> 4, h = bh & 15;
    const int row0 = q0 + wid * 16 + (lane >> 2);
    const float inv0 = 1.0f / l0r, inv1 = 1.0f / l1r;
    const size_t base0 = ((size_t)b_ * S_ + row0) * HID_ + h * D_;
    const size_t base1 = ((size_t)b_ * S_ + row0 + 8) * HID_ + h * D_;
    const int col0 = (lane & 3) * 2;
#pragma unroll
    for (int nt = 0; nt < 16; nt++) {
        int col = 8 * nt + col0;
        float x0 = oa[nt][0] * inv0, y0 = oa[nt][1] * inv0;
        float x1 = oa[nt][2] * inv1, y1 = oa[nt][3] * inv1;
        unsigned short hx, lx, hy, ly;
        split1(x0, hx, lx);
        split1(y0, hy, ly);
        *(uint32_t*)(g_xhi + base0 + col) = (uint32_t)hx | ((uint32_t)hy << 16);
        *(uint32_t*)(g_xlo + base0 + col) = (uint32_t)lx | ((uint32_t)ly << 16);
        split1(x1, hx, lx);
        split1(y1, hy, ly);
        *(uint32_t*)(g_xhi + base1 + col) = (uint32_t)hx | ((uint32_t)hy << 16);
        *(uint32_t*)(g_xlo + base1 + col) = (uint32_t)lx | ((uint32_t)ly << 16);
    }
}

// ---------------------------------------------------------------------------
// Launch
// ---------------------------------------------------------------------------
extern "C" void kernel_launch(void* const* d_in, const int* in_sizes, int n_in,
                              void* d_out, int out_size) {
    const float* X = (const float*)d_in[0];
    const float* cosb = (const float*)d_in[1];
    const float* sinb = (const float*)d_in[2];
    const float* Wq = (const float*)d_in[3];
    const float* Wk = (const float*)d_in[4];
    const float* Wv = (const float*)d_in[5];
    const float* Wo = (const float*)d_in[6];
    float* out = (float*)d_out;

    cudaFuncSetAttribute(mma_gemm<0>, cudaFuncAttributeMaxDynamicSharedMemorySize, GEMM_SMEM);
    cudaFuncSetAttribute(mma_gemm<1>, cudaFuncAttributeMaxDynamicSharedMemorySize, GEMM_SMEM);
    cudaFuncSetAttribute(attn_mma_kernel, cudaFuncAttributeMaxDynamicSharedMemorySize, ATTN_SMEM);

    const dim3 wgrid(64, 64);
    const dim3 wblk(32, 8);

    wsplit_kernel<<<wgrid, wblk>>>(Wq, 0);
    wsplit_kernel<<<wgrid, wblk>>>(Wk, 1);
    wsplit_kernel<<<wgrid, wblk>>>(Wv, 2);
    wsplit_kernel<<<wgrid, wblk>>>(Wo, 3);
    asplit_kernel<<<(M_ * HID_ / 4) / 256, 256>>>(X);

    // fused QKV projection
    mma_gemm<1><<<dim3(48, M_ / 128), 256, GEMM_SMEM>>>(nullptr);

    rope_split_kernel<<<(B_ * H_ * S_ * 64) / 256, 256>>>(cosb, sinb);

    // attention writes g_xhi/g_xlo directly
    attn_mma_kernel<<<dim3(S_ / 128, B_ * H_), 256, ATTN_SMEM>>>();

    // O projection
    mma_gemm<0><<<dim3(HID_ / 128, M_ / 128), 256, GEMM_SMEM>>>(out);
}